// round 10
// baseline (speedup 1.0000x reference)
#include <cuda_runtime.h>
#include <cuda_bf16.h>
#include <cstdint>

#define D_MODEL 1024
#define NHEADS  16
#define DK      64
#define BATCH   4
#define SEQ     2048
#define MROWS   (BATCH * SEQ)   // 8192

// -------- scratch (no allocations allowed; __device__ globals) --------
__device__ __nv_bfloat16 g_xh [MROWS * D_MODEL];
__device__ __nv_bfloat16 g_xl [MROWS * D_MODEL];
__device__ __nv_bfloat16 g_qh [MROWS * D_MODEL];
__device__ __nv_bfloat16 g_ql [MROWS * D_MODEL];
__device__ __nv_bfloat16 g_kh [MROWS * D_MODEL];
__device__ __nv_bfloat16 g_kl [MROWS * D_MODEL];
__device__ __nv_bfloat16 g_vh [MROWS * D_MODEL];
__device__ __nv_bfloat16 g_vl [MROWS * D_MODEL];
__device__ __nv_bfloat16 g_aoh[MROWS * D_MODEL];
__device__ __nv_bfloat16 g_aol[MROWS * D_MODEL];
__device__ __nv_bfloat16 g_wh [4][D_MODEL * D_MODEL];
__device__ __nv_bfloat16 g_wl [4][D_MODEL * D_MODEL];

// ======================================================================
// helpers
// ======================================================================
__device__ __forceinline__ uint32_t smem_u32(const void* p) {
    uint32_t a;
    asm("{ .reg .u64 t; cvta.to.shared.u64 t, %1; cvt.u32.u64 %0, t; }"
        : "=r"(a) : "l"(p));
    return a;
}

#define LDSM_X4(r0, r1, r2, r3, addr)                                         \
    asm volatile("ldmatrix.sync.aligned.m8n8.x4.shared.b16 {%0,%1,%2,%3}, [%4];" \
                 : "=r"(r0), "=r"(r1), "=r"(r2), "=r"(r3) : "r"(addr))

#define LDSM_X4_T(r0, r1, r2, r3, addr)                                       \
    asm volatile("ldmatrix.sync.aligned.m8n8.x4.trans.shared.b16 {%0,%1,%2,%3}, [%4];" \
                 : "=r"(r0), "=r"(r1), "=r"(r2), "=r"(r3) : "r"(addr))

#define MMA16816(d, a, b0v, b1v)                                              \
    asm volatile("mma.sync.aligned.m16n8k16.row.col.f32.bf16.bf16.f32 "       \
                 "{%0,%1,%2,%3}, {%4,%5,%6,%7}, {%8,%9}, {%0,%1,%2,%3};"      \
                 : "+f"((d)[0]), "+f"((d)[1]), "+f"((d)[2]), "+f"((d)[3])     \
                 : "r"((a)[0]), "r"((a)[1]), "r"((a)[2]), "r"((a)[3]),        \
                   "r"(b0v), "r"(b1v))

#define CP_ASYNC16(saddr, gptr)                                               \
    asm volatile("cp.async.cg.shared.global [%0], [%1], 16;"                  \
                 :: "r"(saddr), "l"(gptr))
#define CP_COMMIT() asm volatile("cp.async.commit_group;" ::: "memory")
#define CP_WAIT(n)  asm volatile("cp.async.wait_group %0;" :: "n"(n) : "memory")

// split one float pair into bf16 hi + bf16 lo packed u32s
__device__ __forceinline__ void split2(float x, float y, uint32_t& hi, uint32_t& lo) {
    __nv_bfloat162 h = __floats2bfloat162_rn(x, y);
    float2 f = __bfloat1622float2(h);
    __nv_bfloat162 l = __floats2bfloat162_rn(x - f.x, y - f.y);
    hi = *reinterpret_cast<uint32_t*>(&h);
    lo = *reinterpret_cast<uint32_t*>(&l);
}

// ======================================================================
// presplit: fp32 array -> bf16 hi/lo arrays. 4 elems per thread.
// ======================================================================
__global__ __launch_bounds__(256)
void presplit(const float* __restrict__ in,
              __nv_bfloat16* __restrict__ hi,
              __nv_bfloat16* __restrict__ lo)
{
    const int i = blockIdx.x * 256 + threadIdx.x;
    float4 v = *(const float4*)(in + (size_t)i * 4);
    uint2 h, l;
    split2(v.x, v.y, h.x, l.x);
    split2(v.z, v.w, h.y, l.y);
    *(uint2*)(hi + (size_t)i * 4) = h;
    *(uint2*)(lo + (size_t)i * 4) = l;
}

// ======================================================================
// GEMM mainloop: C = A @ B^T, bf16x3, term-major MMA order, 3-stage pipe.
// ======================================================================
#define GPITCH 80
#define GBK    32
#define GNIT   (D_MODEL / GBK)
#define MAT_B  (128 * GPITCH)          // 10240
#define BUF_B  (4 * MAT_B)             // 40960
#define GSMEM  (3 * BUF_B)             // 122880

__device__ __forceinline__ void gemm_stage(
    uint32_t sbase, uint32_t bufo, int tid, int koff,
    const __nv_bfloat16* Ah, const __nv_bfloat16* Al,
    const __nv_bfloat16* Bh, const __nv_bfloat16* Bl,
    int bm, int bn)
{
    #pragma unroll
    for (int i = 0; i < 2; i++) {
        const int id  = tid + 256 * i;      // 0..511
        const int row = id >> 2;
        const int c16 = id & 3;
        const uint32_t so = sbase + bufo + (uint32_t)(row * GPITCH + c16 * 16);
        const size_t ga = (size_t)(bm + row) * D_MODEL + koff + c16 * 8;
        const size_t gb = (size_t)(bn + row) * D_MODEL + koff + c16 * 8;
        CP_ASYNC16(so,             Ah + ga);
        CP_ASYNC16(so + MAT_B,     Al + ga);
        CP_ASYNC16(so + 2 * MAT_B, Bh + gb);
        CP_ASYNC16(so + 3 * MAT_B, Bl + gb);
    }
}

__device__ __forceinline__ void gemm_mainloop(
    const __nv_bfloat16* __restrict__ Ah, const __nv_bfloat16* __restrict__ Al,
    const __nv_bfloat16* __restrict__ Bh, const __nv_bfloat16* __restrict__ Bl,
    int bm, int bn, uint32_t sbase, int tid, float (&acc)[2][8][4])
{
    const int lane   = tid & 31;
    const int wid    = tid >> 5;
    const int warp_m = wid & 3;
    const int warp_n = wid >> 2;

    const uint32_t a_l = sbase + (uint32_t)((warp_m * 32 + (lane & 15)) * GPITCH
                                            + (lane >> 4) * 16);
    const int bnl = warp_n * 64 + (lane & 7) + ((lane >> 4) << 3);
    const uint32_t b_l = sbase + 2 * MAT_B + (uint32_t)(bnl * GPITCH
                                            + ((lane >> 3) & 1) * 16);

    gemm_stage(sbase, 0,     tid, 0,   Ah, Al, Bh, Bl, bm, bn);
    CP_COMMIT();
    gemm_stage(sbase, BUF_B, tid, GBK, Ah, Al, Bh, Bl, bm, bn);
    CP_COMMIT();

    #pragma unroll 1
    for (int it = 0; it < GNIT; it++) {
        const uint32_t bufo = (uint32_t)(it % 3) * BUF_B;
        if (it + 2 < GNIT) {
            gemm_stage(sbase, (uint32_t)((it + 2) % 3) * BUF_B, tid,
                       (it + 2) * GBK, Ah, Al, Bh, Bl, bm, bn);
            CP_COMMIT();
            CP_WAIT(2);
        } else if (it + 1 < GNIT) {
            CP_WAIT(1);
        } else {
            CP_WAIT(0);
        }
        __syncthreads();

        #pragma unroll
        for (int ks = 0; ks < 2; ks++) {
            const uint32_t ko = (uint32_t)(ks * 32);
            uint32_t ah[2][4], al[2][4];
            #pragma unroll
            for (int im = 0; im < 2; im++) {
                uint32_t aa = a_l + bufo + ko + (uint32_t)(im * 16 * GPITCH);
                LDSM_X4(ah[im][0], ah[im][1], ah[im][2], ah[im][3], aa);
                LDSM_X4(al[im][0], al[im][1], al[im][2], al[im][3], aa + MAT_B);
            }
            uint32_t bh[16], bl[16];
            #pragma unroll
            for (int pn = 0; pn < 4; pn++) {
                uint32_t ba = b_l + bufo + ko + (uint32_t)(pn * 16 * GPITCH);
                LDSM_X4(bh[4 * pn + 0], bh[4 * pn + 1], bh[4 * pn + 2], bh[4 * pn + 3], ba);
                LDSM_X4(bl[4 * pn + 0], bl[4 * pn + 1], bl[4 * pn + 2], bl[4 * pn + 3], ba + MAT_B);
            }
            // term-major: 16 independent MMAs per pass, no RAW chains
            #pragma unroll
            for (int im = 0; im < 2; im++)
                #pragma unroll
                for (int in = 0; in < 8; in++)
                    MMA16816(acc[im][in], ah[im], bh[2 * in], bh[2 * in + 1]);
            #pragma unroll
            for (int im = 0; im < 2; im++)
                #pragma unroll
                for (int in = 0; in < 8; in++)
                    MMA16816(acc[im][in], ah[im], bl[2 * in], bl[2 * in + 1]);
            #pragma unroll
            for (int im = 0; im < 2; im++)
                #pragma unroll
                for (int in = 0; in < 8; in++)
                    MMA16816(acc[im][in], al[im], bh[2 * in], bh[2 * in + 1]);
        }
        __syncthreads();
    }
}

// ---- fused QKV projection: gridDim.z selects weight + destination ----
__global__ __launch_bounds__(256)
void qkv_mma(const __nv_bfloat16* __restrict__ xh,
             const __nv_bfloat16* __restrict__ xl,
             const __nv_bfloat16* __restrict__ wh,
             const __nv_bfloat16* __restrict__ wl,
             __nv_bfloat16* __restrict__ qh, __nv_bfloat16* __restrict__ ql,
             __nv_bfloat16* __restrict__ kh, __nv_bfloat16* __restrict__ kl,
             __nv_bfloat16* __restrict__ vh, __nv_bfloat16* __restrict__ vl)
{
    extern __shared__ char sm[];
    const uint32_t sbase = smem_u32(sm);
    const int tid = threadIdx.x;
    const int z   = blockIdx.z;
    const int bm  = blockIdx.y * 128;
    const int bn  = blockIdx.x * 128;
    const size_t WN = (size_t)D_MODEL * D_MODEL;

    float acc[2][8][4];
    #pragma unroll
    for (int i = 0; i < 2; i++)
        #pragma unroll
        for (int j = 0; j < 8; j++)
            #pragma unroll
            for (int r = 0; r < 4; r++) acc[i][j][r] = 0.f;

    gemm_mainloop(xh, xl, wh + (size_t)z * WN, wl + (size_t)z * WN,
                  bm, bn, sbase, tid, acc);

    __nv_bfloat16* Ch = (z == 0) ? qh : (z == 1) ? kh : vh;
    __nv_bfloat16* Cl = (z == 0) ? ql : (z == 1) ? kl : vl;
    const float s = (z == 0) ? 0.125f : 1.f;

    const int lane = tid & 31;
    const int wid  = tid >> 5;
    const int g    = lane >> 2;
    const int q4   = (lane & 3) * 2;
    #pragma unroll
    for (int im = 0; im < 2; im++) {
        const int r0 = bm + (wid & 3) * 32 + im * 16 + g;
        #pragma unroll
        for (int in = 0; in < 8; in++) {
            const int c = bn + (wid >> 2) * 64 + in * 8 + q4;
            uint32_t h, l;
            split2(acc[im][in][0] * s, acc[im][in][1] * s, h, l);
            *(uint32_t*)(Ch + (size_t)r0 * D_MODEL + c) = h;
            *(uint32_t*)(Cl + (size_t)r0 * D_MODEL + c) = l;
            split2(acc[im][in][2] * s, acc[im][in][3] * s, h, l);
            *(uint32_t*)(Ch + (size_t)(r0 + 8) * D_MODEL + c) = h;
            *(uint32_t*)(Cl + (size_t)(r0 + 8) * D_MODEL + c) = l;
        }
    }
}

// ---- output projection: fp32 out + bias ----
__global__ __launch_bounds__(256)
void oproj_mma(const __nv_bfloat16* __restrict__ Ah,
               const __nv_bfloat16* __restrict__ Al,
               const __nv_bfloat16* __restrict__ Bh,
               const __nv_bfloat16* __restrict__ Bl,
               const float* __restrict__ bias,
               float* __restrict__ C)
{
    extern __shared__ char sm[];
    const uint32_t sbase = smem_u32(sm);
    const int tid = threadIdx.x;
    const int bm  = blockIdx.y * 128;
    const int bn  = blockIdx.x * 128;

    float acc[2][8][4];
    #pragma unroll
    for (int i = 0; i < 2; i++)
        #pragma unroll
        for (int j = 0; j < 8; j++)
            #pragma unroll
            for (int r = 0; r < 4; r++) acc[i][j][r] = 0.f;

    gemm_mainloop(Ah, Al, Bh, Bl, bm, bn, sbase, tid, acc);

    const int lane = tid & 31;
    const int wid  = tid >> 5;
    const int g    = lane >> 2;
    const int q4   = (lane & 3) * 2;
    #pragma unroll
    for (int im = 0; im < 2; im++) {
        const int r0 = bm + (wid & 3) * 32 + im * 16 + g;
        #pragma unroll
        for (int in = 0; in < 8; in++) {
            const int c = bn + (wid >> 2) * 64 + in * 8 + q4;
            const float b0 = bias[c], b1 = bias[c + 1];
            *(float2*)(C + (size_t)r0 * D_MODEL + c) =
                make_float2(acc[im][in][0] + b0, acc[im][in][1] + b1);
            *(float2*)(C + (size_t)(r0 + 8) * D_MODEL + c) =
                make_float2(acc[im][in][2] + b0, acc[im][in][3] + b1);
        }
    }
}

// ======================================================================
// Tensor-core causal flash attention, term-major MMA order.
// ======================================================================
#define APITCH 144
#define SQL   (128 * APITCH)            // 18432
#define KV0   (2 * 128 * APITCH)        // 36864
#define KVMAT (64 * APITCH)             // 9216
#define KVBUF (4 * KVMAT)               // 36864
#define ASMEM (KV0 + 2 * KVBUF)         // 110592

__device__ __forceinline__ void attn_stage_kv(
    uint32_t dst, int tid, const __nv_bfloat16* Kh, const __nv_bfloat16* Kl,
    const __nv_bfloat16* Vh, const __nv_bfloat16* Vl,
    size_t gbase, int k0)
{
    #pragma unroll
    for (int i = 0; i < 2; i++) {
        const int id  = tid + 256 * i;        // 0..511
        const int row = id >> 3;              // 0..63
        const int c16 = id & 7;
        const uint32_t so = dst + (uint32_t)(row * APITCH + c16 * 16);
        const size_t gk = gbase + (size_t)(k0 + row) * D_MODEL + c16 * 8;
        CP_ASYNC16(so,             Kh + gk);
        CP_ASYNC16(so + KVMAT,     Kl + gk);
        CP_ASYNC16(so + 2 * KVMAT, Vh + gk);
        CP_ASYNC16(so + 3 * KVMAT, Vl + gk);
    }
}

__global__ __launch_bounds__(256)
void attn_mma(const __nv_bfloat16* __restrict__ Qh,
              const __nv_bfloat16* __restrict__ Ql,
              const __nv_bfloat16* __restrict__ Kh,
              const __nv_bfloat16* __restrict__ Kl,
              const __nv_bfloat16* __restrict__ Vh,
              const __nv_bfloat16* __restrict__ Vl,
              __nv_bfloat16* __restrict__ Oh,
              __nv_bfloat16* __restrict__ Ol)
{
    extern __shared__ char sm[];
    const uint32_t sbase = smem_u32(sm);

    const int tid  = threadIdx.x;
    const int lane = tid & 31;
    const int wid  = tid >> 5;
    const int g    = lane >> 2;
    const int tg   = lane & 3;
    const int qb   = gridDim.x - 1 - blockIdx.x;   // heavy blocks first
    const int bh   = blockIdx.y;
    const size_t base = (size_t)(bh >> 4) * SEQ * D_MODEL + (size_t)(bh & 15) * DK;

    const int qbase = qb * 128 + wid * 16;

    // ---- stage Q (cp.async, once) ----
    #pragma unroll
    for (int i = 0; i < 4; i++) {
        const int id  = tid + 256 * i;
        const int row = id >> 3;
        const int c16 = id & 7;
        const uint32_t so = sbase + (uint32_t)(row * APITCH + c16 * 16);
        const size_t gq = base + (size_t)(qb * 128 + row) * D_MODEL + c16 * 8;
        CP_ASYNC16(so,       Qh + gq);
        CP_ASYNC16(so + SQL, Ql + gq);
    }
    attn_stage_kv(sbase + KV0, tid, Kh, Kl, Vh, Vl, base, 0);
    CP_COMMIT();

    float oacc[8][4];
    #pragma unroll
    for (int i = 0; i < 8; i++)
        #pragma unroll
        for (int r = 0; r < 4; r++) oacc[i][r] = 0.f;
    float m0 = -1e30f, m1 = -1e30f, l0 = 0.f, l1 = 0.f;

    const uint32_t qa = sbase + (uint32_t)((wid * 16 + (lane & 15)) * APITCH
                                           + (lane >> 4) * 16);
    const uint32_t ka_l = (uint32_t)(((lane & 7) + ((lane >> 4) << 3)) * APITCH
                                           + ((lane >> 3) & 1) * 16);
    const uint32_t va_l = (uint32_t)((lane & 15) * APITCH + (lane >> 4) * 16);

    const int ntiles = 2 * qb + 2;

    #pragma unroll 1
    for (int t = 0; t < ntiles; t++) {
        const int k0 = t * 64;
        const uint32_t kvb = sbase + KV0 + (uint32_t)(t & 1) * KVBUF;

        if (t + 1 < ntiles) {
            attn_stage_kv(sbase + KV0 + (uint32_t)((t + 1) & 1) * KVBUF,
                          tid, Kh, Kl, Vh, Vl, base, (t + 1) * 64);
            CP_COMMIT();
            CP_WAIT(1);
        } else {
            CP_WAIT(0);
        }
        __syncthreads();

        const bool active = (k0 <= qbase + 15);
        if (active) {
            // ---- S = Q @ K^T (term-major) ----
            float sacc[8][4];
            #pragma unroll
            for (int i = 0; i < 8; i++)
                #pragma unroll
                for (int r = 0; r < 4; r++) sacc[i][r] = 0.f;

            const uint32_t ka = kvb + ka_l;
            #pragma unroll
            for (int kk = 0; kk < 4; kk++) {
                const uint32_t ko = (uint32_t)(kk * 32);
                uint32_t ah[4], al[4];
                LDSM_X4(ah[0], ah[1], ah[2], ah[3], qa + ko);
                LDSM_X4(al[0], al[1], al[2], al[3], qa + ko + SQL);
                uint32_t kh[16], kl[16];
                #pragma unroll
                for (int nt = 0; nt < 4; nt++) {
                    uint32_t ba = ka + ko + (uint32_t)(nt * 16 * APITCH);
                    LDSM_X4(kh[4*nt+0], kh[4*nt+1], kh[4*nt+2], kh[4*nt+3], ba);
                    LDSM_X4(kl[4*nt+0], kl[4*nt+1], kl[4*nt+2], kl[4*nt+3], ba + KVMAT);
                }
                #pragma unroll
                for (int nt = 0; nt < 4; nt++) {
                    MMA16816(sacc[2*nt],   ah, kh[4*nt+0], kh[4*nt+1]);
                    MMA16816(sacc[2*nt+1], ah, kh[4*nt+2], kh[4*nt+3]);
                }
                #pragma unroll
                for (int nt = 0; nt < 4; nt++) {
                    MMA16816(sacc[2*nt],   ah, kl[4*nt+0], kl[4*nt+1]);
                    MMA16816(sacc[2*nt+1], ah, kl[4*nt+2], kl[4*nt+3]);
                }
                #pragma unroll
                for (int nt = 0; nt < 4; nt++) {
                    MMA16816(sacc[2*nt],   al, kh[4*nt+0], kh[4*nt+1]);
                    MMA16816(sacc[2*nt+1], al, kh[4*nt+2], kh[4*nt+3]);
                }
            }

            // ---- causal mask ----
            if (t + 2 >= ntiles) {
                const int qi0 = qbase + g;
                const int qi1 = qbase + g + 8;
                #pragma unroll
                for (int dn = 0; dn < 8; dn++) {
                    const int kc = k0 + dn * 8 + tg * 2;
                    if (kc     > qi0) sacc[dn][0] = -1e30f;
                    if (kc + 1 > qi0) sacc[dn][1] = -1e30f;
                    if (kc     > qi1) sacc[dn][2] = -1e30f;
                    if (kc + 1 > qi1) sacc[dn][3] = -1e30f;
                }
            }

            // ---- online softmax ----
            float r0 = -1e30f, r1 = -1e30f;
            #pragma unroll
            for (int dn = 0; dn < 8; dn++) {
                r0 = fmaxf(r0, fmaxf(sacc[dn][0], sacc[dn][1]));
                r1 = fmaxf(r1, fmaxf(sacc[dn][2], sacc[dn][3]));
            }
            r0 = fmaxf(r0, __shfl_xor_sync(0xFFFFFFFFu, r0, 1));
            r0 = fmaxf(r0, __shfl_xor_sync(0xFFFFFFFFu, r0, 2));
            r1 = fmaxf(r1, __shfl_xor_sync(0xFFFFFFFFu, r1, 1));
            r1 = fmaxf(r1, __shfl_xor_sync(0xFFFFFFFFu, r1, 2));
            const float nm0 = fmaxf(m0, r0), nm1 = fmaxf(m1, r1);
            const float c0 = __expf(m0 - nm0), c1 = __expf(m1 - nm1);
            m0 = nm0; m1 = nm1;
            l0 *= c0;  l1 *= c1;
            #pragma unroll
            for (int dn = 0; dn < 8; dn++) {
                oacc[dn][0] *= c0; oacc[dn][1] *= c0;
                oacc[dn][2] *= c1; oacc[dn][3] *= c1;
            }
            #pragma unroll
            for (int dn = 0; dn < 8; dn++) {
                float p0 = __expf(sacc[dn][0] - m0);
                float p1 = __expf(sacc[dn][1] - m0);
                float p2 = __expf(sacc[dn][2] - m1);
                float p3 = __expf(sacc[dn][3] - m1);
                sacc[dn][0] = p0; sacc[dn][1] = p1;
                sacc[dn][2] = p2; sacc[dn][3] = p3;
                l0 += p0 + p1; l1 += p2 + p3;
            }

            // ---- O += P @ V (term-major) ----
            const uint32_t va = kvb + 2 * KVMAT + va_l;
            #pragma unroll
            for (int kk = 0; kk < 4; kk++) {
                uint32_t ph[4], pl[4];
                split2(sacc[2*kk][0],   sacc[2*kk][1],   ph[0], pl[0]);
                split2(sacc[2*kk][2],   sacc[2*kk][3],   ph[1], pl[1]);
                split2(sacc[2*kk+1][0], sacc[2*kk+1][1], ph[2], pl[2]);
                split2(sacc[2*kk+1][2], sacc[2*kk+1][3], ph[3], pl[3]);
                uint32_t vh[16], vl[16];
                #pragma unroll
                for (int dn = 0; dn < 4; dn++) {
                    uint32_t a = va + (uint32_t)(kk * 16 * APITCH + dn * 32);
                    LDSM_X4_T(vh[4*dn+0], vh[4*dn+1], vh[4*dn+2], vh[4*dn+3], a);
                    LDSM_X4_T(vl[4*dn+0], vl[4*dn+1], vl[4*dn+2], vl[4*dn+3], a + KVMAT);
                }
                #pragma unroll
                for (int dn = 0; dn < 4; dn++) {
                    MMA16816(oacc[2*dn],   ph, vh[4*dn+0], vh[4*dn+1]);
                    MMA16816(oacc[2*dn+1], ph, vh[4*dn+2], vh[4*dn+3]);
                }
                #pragma unroll
                for (int dn = 0; dn < 4; dn++) {
                    MMA16816(oacc[2*dn],   ph, vl[4*dn+0], vl[4*dn+1]);
                    MMA16816(oacc[2*dn+1], ph, vl[4*dn+2], vl[4*dn+3]);
                }
                #pragma unroll
                for (int dn = 0; dn < 4; dn++) {
                    MMA16816(oacc[2*dn],   pl, vh[4*dn+0], vh[4*dn+1]);
                    MMA16816(oacc[2*dn+1], pl, vh[4*dn+2], vh[4*dn+3]);
                }
            }
        }
        __syncthreads();
    }

    // ---- epilogue: normalize, split, store ----
    l0 += __shfl_xor_sync(0xFFFFFFFFu, l0, 1);
    l0 += __shfl_xor_sync(0xFFFFFFFFu, l0, 2);
    l1 += __shfl_xor_sync(0xFFFFFFFFu, l1, 1);
    l1 += __shfl_xor_sync(0xFFFFFFFFu, l1, 2);
    const float inv0 = 1.f / l0, inv1 = 1.f / l1;

    const size_t o0 = base + (size_t)(qbase + g) * D_MODEL + tg * 2;
    const size_t o1 = o0 + 8 * D_MODEL;
    #pragma unroll
    for (int dn = 0; dn < 8; dn++) {
        uint32_t h, l;
        split2(oacc[dn][0] * inv0, oacc[dn][1] * inv0, h, l);
        *(uint32_t*)(Oh + o0 + dn * 8) = h;
        *(uint32_t*)(Ol + o0 + dn * 8) = l;
        split2(oacc[dn][2] * inv1, oacc[dn][3] * inv1, h, l);
        *(uint32_t*)(Oh + o1 + dn * 8) = h;
        *(uint32_t*)(Ol + o1 + dn * 8) = l;
    }
}

// ======================================================================
extern "C" void kernel_launch(void* const* d_in, const int* in_sizes, int n_in,
                              void* d_out, int out_size)
{
    const float* x   = (const float*)d_in[0];
    const float* w_q = (const float*)d_in[1];
    const float* w_k = (const float*)d_in[2];
    const float* w_v = (const float*)d_in[3];
    const float* w_o = (const float*)d_in[4];
    const float* b_o = (const float*)d_in[5];
    float* out = (float*)d_out;

    __nv_bfloat16 *xh, *xl, *qh, *ql, *kh, *kl, *vh, *vl, *aoh, *aol, *wh, *wl;
    cudaGetSymbolAddress((void**)&xh,  g_xh);
    cudaGetSymbolAddress((void**)&xl,  g_xl);
    cudaGetSymbolAddress((void**)&qh,  g_qh);
    cudaGetSymbolAddress((void**)&ql,  g_ql);
    cudaGetSymbolAddress((void**)&kh,  g_kh);
    cudaGetSymbolAddress((void**)&kl,  g_kl);
    cudaGetSymbolAddress((void**)&vh,  g_vh);
    cudaGetSymbolAddress((void**)&vl,  g_vl);
    cudaGetSymbolAddress((void**)&aoh, g_aoh);
    cudaGetSymbolAddress((void**)&aol, g_aol);
    cudaGetSymbolAddress((void**)&wh,  g_wh);
    cudaGetSymbolAddress((void**)&wl,  g_wl);

    cudaFuncSetAttribute(qkv_mma,   cudaFuncAttributeMaxDynamicSharedMemorySize, GSMEM);
    cudaFuncSetAttribute(oproj_mma, cudaFuncAttributeMaxDynamicSharedMemorySize, GSMEM);
    cudaFuncSetAttribute(attn_mma,  cudaFuncAttributeMaxDynamicSharedMemorySize, ASMEM);

    const size_t WN = (size_t)D_MODEL * D_MODEL;

    presplit<<<MROWS * D_MODEL / 1024, 256>>>(x, xh, xl);
    presplit<<<(int)(WN / 1024), 256>>>(w_q, wh + 0 * WN, wl + 0 * WN);
    presplit<<<(int)(WN / 1024), 256>>>(w_k, wh + 1 * WN, wl + 1 * WN);
    presplit<<<(int)(WN / 1024), 256>>>(w_v, wh + 2 * WN, wl + 2 * WN);
    presplit<<<(int)(WN / 1024), 256>>>(w_o, wh + 3 * WN, wl + 3 * WN);

    dim3 qgrid(D_MODEL / 128, MROWS / 128, 3);   // (8, 64, 3)
    qkv_mma<<<qgrid, 256, GSMEM>>>(xh, xl, wh, wl, qh, ql, kh, kl, vh, vl);

    dim3 agrid(SEQ / 128, BATCH * NHEADS);       // (16, 64)
    attn_mma<<<agrid, 256, ASMEM>>>(qh, ql, kh, kl, vh, vl, aoh, aol);

    dim3 ogrid(D_MODEL / 128, MROWS / 128);      // (8, 64)
    oproj_mma<<<ogrid, 256, GSMEM>>>(aoh, aol, wh + 3 * WN, wl + 3 * WN, b_o, out);
}

// round 11
// speedup vs baseline: 1.1578x; 1.1578x over previous
#include <cuda_runtime.h>
#include <cuda_bf16.h>
#include <cstdint>

#define D_MODEL 1024
#define NHEADS  16
#define DK      64
#define BATCH   4
#define SEQ     2048
#define MROWS   (BATCH * SEQ)   // 8192

// -------- scratch (no allocations allowed; __device__ globals) --------
__device__ __nv_bfloat16 g_xh [MROWS * D_MODEL];
__device__ __nv_bfloat16 g_xl [MROWS * D_MODEL];
__device__ __nv_bfloat16 g_qh [MROWS * D_MODEL];
__device__ __nv_bfloat16 g_ql [MROWS * D_MODEL];
__device__ __nv_bfloat16 g_kh [MROWS * D_MODEL];
__device__ __nv_bfloat16 g_kl [MROWS * D_MODEL];
__device__ __nv_bfloat16 g_vh [MROWS * D_MODEL];
__device__ __nv_bfloat16 g_vl [MROWS * D_MODEL];
__device__ __nv_bfloat16 g_aoh[MROWS * D_MODEL];
__device__ __nv_bfloat16 g_aol[MROWS * D_MODEL];
__device__ __nv_bfloat16 g_wh [4][D_MODEL * D_MODEL];
__device__ __nv_bfloat16 g_wl [4][D_MODEL * D_MODEL];

// ======================================================================
// helpers
// ======================================================================
__device__ __forceinline__ uint32_t smem_u32(const void* p) {
    uint32_t a;
    asm("{ .reg .u64 t; cvta.to.shared.u64 t, %1; cvt.u32.u64 %0, t; }"
        : "=r"(a) : "l"(p));
    return a;
}

#define LDSM_X4(r0, r1, r2, r3, addr)                                         \
    asm volatile("ldmatrix.sync.aligned.m8n8.x4.shared.b16 {%0,%1,%2,%3}, [%4];" \
                 : "=r"(r0), "=r"(r1), "=r"(r2), "=r"(r3) : "r"(addr))

#define LDSM_X4_T(r0, r1, r2, r3, addr)                                       \
    asm volatile("ldmatrix.sync.aligned.m8n8.x4.trans.shared.b16 {%0,%1,%2,%3}, [%4];" \
                 : "=r"(r0), "=r"(r1), "=r"(r2), "=r"(r3) : "r"(addr))

#define MMA16816(d, a, b0v, b1v)                                              \
    asm volatile("mma.sync.aligned.m16n8k16.row.col.f32.bf16.bf16.f32 "       \
                 "{%0,%1,%2,%3}, {%4,%5,%6,%7}, {%8,%9}, {%0,%1,%2,%3};"      \
                 : "+f"((d)[0]), "+f"((d)[1]), "+f"((d)[2]), "+f"((d)[3])     \
                 : "r"((a)[0]), "r"((a)[1]), "r"((a)[2]), "r"((a)[3]),        \
                   "r"(b0v), "r"(b1v))

#define CP_ASYNC16(saddr, gptr)                                               \
    asm volatile("cp.async.cg.shared.global [%0], [%1], 16;"                  \
                 :: "r"(saddr), "l"(gptr))
#define CP_COMMIT() asm volatile("cp.async.commit_group;" ::: "memory")
#define CP_WAIT(n)  asm volatile("cp.async.wait_group %0;" :: "n"(n) : "memory")

// split one float pair into bf16 hi + bf16 lo packed u32s
__device__ __forceinline__ void split2(float x, float y, uint32_t& hi, uint32_t& lo) {
    __nv_bfloat162 h = __floats2bfloat162_rn(x, y);
    float2 f = __bfloat1622float2(h);
    __nv_bfloat162 l = __floats2bfloat162_rn(x - f.x, y - f.y);
    hi = *reinterpret_cast<uint32_t*>(&h);
    lo = *reinterpret_cast<uint32_t*>(&l);
}

// ======================================================================
// fused presplit: x + 4 weights in ONE launch. 1024 elems per block.
// ======================================================================
__global__ __launch_bounds__(256)
void presplit_all(const float* __restrict__ x,
                  const float* __restrict__ wq, const float* __restrict__ wk,
                  const float* __restrict__ wv, const float* __restrict__ wo,
                  __nv_bfloat16* __restrict__ xh, __nv_bfloat16* __restrict__ xl,
                  __nv_bfloat16* __restrict__ wh, __nv_bfloat16* __restrict__ wl)
{
    const int b = blockIdx.x;
    const size_t WN = (size_t)D_MODEL * D_MODEL;
    const float* in;
    __nv_bfloat16 *hi, *lo;
    size_t eo;
    if (b < MROWS) {                       // x: 8192 blocks
        in = x; hi = xh; lo = xl;
        eo = (size_t)b * 1024;
    } else {                               // weights: 1024 blocks each
        const int r = b - MROWS;
        const int w = r >> 10;
        in = (w == 0) ? wq : (w == 1) ? wk : (w == 2) ? wv : wo;
        hi = wh + (size_t)w * WN;
        lo = wl + (size_t)w * WN;
        eo = (size_t)(r & 1023) * 1024;
    }
    const size_t i = eo + (size_t)threadIdx.x * 4;
    float4 v = *(const float4*)(in + i);
    uint2 h, l;
    split2(v.x, v.y, h.x, l.x);
    split2(v.z, v.w, h.y, l.y);
    *(uint2*)(hi + i) = h;
    *(uint2*)(lo + i) = l;
}

// ======================================================================
// GEMM mainloop: C = A @ B^T, bf16x3, term-major MMA order, 2-stage pipe.
// 80 KB smem -> 2 CTAs/SM.
// ======================================================================
#define GPITCH 80
#define GBK    32
#define GNIT   (D_MODEL / GBK)
#define MAT_B  (128 * GPITCH)          // 10240
#define BUF_B  (4 * MAT_B)             // 40960
#define GSMEM  (2 * BUF_B)             // 81920

__device__ __forceinline__ void gemm_stage(
    uint32_t sbase, uint32_t bufo, int tid, int koff,
    const __nv_bfloat16* Ah, const __nv_bfloat16* Al,
    const __nv_bfloat16* Bh, const __nv_bfloat16* Bl,
    int bm, int bn)
{
    #pragma unroll
    for (int i = 0; i < 2; i++) {
        const int id  = tid + 256 * i;      // 0..511
        const int row = id >> 2;
        const int c16 = id & 3;
        const uint32_t so = sbase + bufo + (uint32_t)(row * GPITCH + c16 * 16);
        const size_t ga = (size_t)(bm + row) * D_MODEL + koff + c16 * 8;
        const size_t gb = (size_t)(bn + row) * D_MODEL + koff + c16 * 8;
        CP_ASYNC16(so,             Ah + ga);
        CP_ASYNC16(so + MAT_B,     Al + ga);
        CP_ASYNC16(so + 2 * MAT_B, Bh + gb);
        CP_ASYNC16(so + 3 * MAT_B, Bl + gb);
    }
}

__device__ __forceinline__ void gemm_mainloop(
    const __nv_bfloat16* __restrict__ Ah, const __nv_bfloat16* __restrict__ Al,
    const __nv_bfloat16* __restrict__ Bh, const __nv_bfloat16* __restrict__ Bl,
    int bm, int bn, uint32_t sbase, int tid, float (&acc)[2][8][4])
{
    const int lane   = tid & 31;
    const int wid    = tid >> 5;
    const int warp_m = wid & 3;
    const int warp_n = wid >> 2;

    const uint32_t a_l = sbase + (uint32_t)((warp_m * 32 + (lane & 15)) * GPITCH
                                            + (lane >> 4) * 16);
    const int bnl = warp_n * 64 + (lane & 7) + ((lane >> 4) << 3);
    const uint32_t b_l = sbase + 2 * MAT_B + (uint32_t)(bnl * GPITCH
                                            + ((lane >> 3) & 1) * 16);

    gemm_stage(sbase, 0, tid, 0, Ah, Al, Bh, Bl, bm, bn);
    CP_COMMIT();

    #pragma unroll 1
    for (int it = 0; it < GNIT; it++) {
        const uint32_t bufo = (uint32_t)(it & 1) * BUF_B;
        if (it + 1 < GNIT) {
            gemm_stage(sbase, (uint32_t)((it + 1) & 1) * BUF_B, tid,
                       (it + 1) * GBK, Ah, Al, Bh, Bl, bm, bn);
            CP_COMMIT();
            CP_WAIT(1);
        } else {
            CP_WAIT(0);
        }
        __syncthreads();

        #pragma unroll
        for (int ks = 0; ks < 2; ks++) {
            const uint32_t ko = (uint32_t)(ks * 32);
            uint32_t ah[2][4], al[2][4];
            #pragma unroll
            for (int im = 0; im < 2; im++) {
                uint32_t aa = a_l + bufo + ko + (uint32_t)(im * 16 * GPITCH);
                LDSM_X4(ah[im][0], ah[im][1], ah[im][2], ah[im][3], aa);
                LDSM_X4(al[im][0], al[im][1], al[im][2], al[im][3], aa + MAT_B);
            }
            uint32_t bh[16], bl[16];
            #pragma unroll
            for (int pn = 0; pn < 4; pn++) {
                uint32_t ba = b_l + bufo + ko + (uint32_t)(pn * 16 * GPITCH);
                LDSM_X4(bh[4 * pn + 0], bh[4 * pn + 1], bh[4 * pn + 2], bh[4 * pn + 3], ba);
                LDSM_X4(bl[4 * pn + 0], bl[4 * pn + 1], bl[4 * pn + 2], bl[4 * pn + 3], ba + MAT_B);
            }
            // term-major: 16 independent MMAs per pass, no RAW chains
            #pragma unroll
            for (int im = 0; im < 2; im++)
                #pragma unroll
                for (int in = 0; in < 8; in++)
                    MMA16816(acc[im][in], ah[im], bh[2 * in], bh[2 * in + 1]);
            #pragma unroll
            for (int im = 0; im < 2; im++)
                #pragma unroll
                for (int in = 0; in < 8; in++)
                    MMA16816(acc[im][in], ah[im], bl[2 * in], bl[2 * in + 1]);
            #pragma unroll
            for (int im = 0; im < 2; im++)
                #pragma unroll
                for (int in = 0; in < 8; in++)
                    MMA16816(acc[im][in], al[im], bh[2 * in], bh[2 * in + 1]);
        }
        __syncthreads();
    }
}

// ---- fused QKV projection: gridDim.z selects weight + destination ----
__global__ __launch_bounds__(256, 2)
void qkv_mma(const __nv_bfloat16* __restrict__ xh,
             const __nv_bfloat16* __restrict__ xl,
             const __nv_bfloat16* __restrict__ wh,
             const __nv_bfloat16* __restrict__ wl,
             __nv_bfloat16* __restrict__ qh, __nv_bfloat16* __restrict__ ql,
             __nv_bfloat16* __restrict__ kh, __nv_bfloat16* __restrict__ kl,
             __nv_bfloat16* __restrict__ vh, __nv_bfloat16* __restrict__ vl)
{
    extern __shared__ char sm[];
    const uint32_t sbase = smem_u32(sm);
    const int tid = threadIdx.x;
    const int z   = blockIdx.z;
    const int bm  = blockIdx.y * 128;
    const int bn  = blockIdx.x * 128;
    const size_t WN = (size_t)D_MODEL * D_MODEL;

    float acc[2][8][4];
    #pragma unroll
    for (int i = 0; i < 2; i++)
        #pragma unroll
        for (int j = 0; j < 8; j++)
            #pragma unroll
            for (int r = 0; r < 4; r++) acc[i][j][r] = 0.f;

    gemm_mainloop(xh, xl, wh + (size_t)z * WN, wl + (size_t)z * WN,
                  bm, bn, sbase, tid, acc);

    __nv_bfloat16* Ch = (z == 0) ? qh : (z == 1) ? kh : vh;
    __nv_bfloat16* Cl = (z == 0) ? ql : (z == 1) ? kl : vl;
    const float s = (z == 0) ? 0.125f : 1.f;

    const int lane = tid & 31;
    const int wid  = tid >> 5;
    const int g    = lane >> 2;
    const int q4   = (lane & 3) * 2;
    #pragma unroll
    for (int im = 0; im < 2; im++) {
        const int r0 = bm + (wid & 3) * 32 + im * 16 + g;
        #pragma unroll
        for (int in = 0; in < 8; in++) {
            const int c = bn + (wid >> 2) * 64 + in * 8 + q4;
            uint32_t h, l;
            split2(acc[im][in][0] * s, acc[im][in][1] * s, h, l);
            *(uint32_t*)(Ch + (size_t)r0 * D_MODEL + c) = h;
            *(uint32_t*)(Cl + (size_t)r0 * D_MODEL + c) = l;
            split2(acc[im][in][2] * s, acc[im][in][3] * s, h, l);
            *(uint32_t*)(Ch + (size_t)(r0 + 8) * D_MODEL + c) = h;
            *(uint32_t*)(Cl + (size_t)(r0 + 8) * D_MODEL + c) = l;
        }
    }
}

// ---- output projection: fp32 out + bias ----
__global__ __launch_bounds__(256, 2)
void oproj_mma(const __nv_bfloat16* __restrict__ Ah,
               const __nv_bfloat16* __restrict__ Al,
               const __nv_bfloat16* __restrict__ Bh,
               const __nv_bfloat16* __restrict__ Bl,
               const float* __restrict__ bias,
               float* __restrict__ C)
{
    extern __shared__ char sm[];
    const uint32_t sbase = smem_u32(sm);
    const int tid = threadIdx.x;
    const int bm  = blockIdx.y * 128;
    const int bn  = blockIdx.x * 128;

    float acc[2][8][4];
    #pragma unroll
    for (int i = 0; i < 2; i++)
        #pragma unroll
        for (int j = 0; j < 8; j++)
            #pragma unroll
            for (int r = 0; r < 4; r++) acc[i][j][r] = 0.f;

    gemm_mainloop(Ah, Al, Bh, Bl, bm, bn, sbase, tid, acc);

    const int lane = tid & 31;
    const int wid  = tid >> 5;
    const int g    = lane >> 2;
    const int q4   = (lane & 3) * 2;
    #pragma unroll
    for (int im = 0; im < 2; im++) {
        const int r0 = bm + (wid & 3) * 32 + im * 16 + g;
        #pragma unroll
        for (int in = 0; in < 8; in++) {
            const int c = bn + (wid >> 2) * 64 + in * 8 + q4;
            const float b0 = bias[c], b1 = bias[c + 1];
            *(float2*)(C + (size_t)r0 * D_MODEL + c) =
                make_float2(acc[im][in][0] + b0, acc[im][in][1] + b1);
            *(float2*)(C + (size_t)(r0 + 8) * D_MODEL + c) =
                make_float2(acc[im][in][2] + b0, acc[im][in][3] + b1);
        }
    }
}

// ======================================================================
// Tensor-core causal flash attention (R8 MMA ordering, reversed CTA order).
// ======================================================================
#define APITCH 144
#define SQL   (128 * APITCH)            // 18432
#define KV0   (2 * 128 * APITCH)        // 36864
#define KVMAT (64 * APITCH)             // 9216
#define KVBUF (4 * KVMAT)               // 36864
#define ASMEM (KV0 + 2 * KVBUF)         // 110592

__device__ __forceinline__ void attn_stage_kv(
    uint32_t dst, int tid, const __nv_bfloat16* Kh, const __nv_bfloat16* Kl,
    const __nv_bfloat16* Vh, const __nv_bfloat16* Vl,
    size_t gbase, int k0)
{
    #pragma unroll
    for (int i = 0; i < 2; i++) {
        const int id  = tid + 256 * i;        // 0..511
        const int row = id >> 3;              // 0..63
        const int c16 = id & 7;
        const uint32_t so = dst + (uint32_t)(row * APITCH + c16 * 16);
        const size_t gk = gbase + (size_t)(k0 + row) * D_MODEL + c16 * 8;
        CP_ASYNC16(so,             Kh + gk);
        CP_ASYNC16(so + KVMAT,     Kl + gk);
        CP_ASYNC16(so + 2 * KVMAT, Vh + gk);
        CP_ASYNC16(so + 3 * KVMAT, Vl + gk);
    }
}

__global__ __launch_bounds__(256)
void attn_mma(const __nv_bfloat16* __restrict__ Qh,
              const __nv_bfloat16* __restrict__ Ql,
              const __nv_bfloat16* __restrict__ Kh,
              const __nv_bfloat16* __restrict__ Kl,
              const __nv_bfloat16* __restrict__ Vh,
              const __nv_bfloat16* __restrict__ Vl,
              __nv_bfloat16* __restrict__ Oh,
              __nv_bfloat16* __restrict__ Ol)
{
    extern __shared__ char sm[];
    const uint32_t sbase = smem_u32(sm);

    const int tid  = threadIdx.x;
    const int lane = tid & 31;
    const int wid  = tid >> 5;
    const int g    = lane >> 2;
    const int tg   = lane & 3;
    const int qb   = gridDim.x - 1 - blockIdx.x;   // heavy blocks first
    const int bh   = blockIdx.y;
    const size_t base = (size_t)(bh >> 4) * SEQ * D_MODEL + (size_t)(bh & 15) * DK;

    const int qbase = qb * 128 + wid * 16;

    // ---- stage Q (cp.async, once) ----
    #pragma unroll
    for (int i = 0; i < 4; i++) {
        const int id  = tid + 256 * i;
        const int row = id >> 3;
        const int c16 = id & 7;
        const uint32_t so = sbase + (uint32_t)(row * APITCH + c16 * 16);
        const size_t gq = base + (size_t)(qb * 128 + row) * D_MODEL + c16 * 8;
        CP_ASYNC16(so,       Qh + gq);
        CP_ASYNC16(so + SQL, Ql + gq);
    }
    attn_stage_kv(sbase + KV0, tid, Kh, Kl, Vh, Vl, base, 0);
    CP_COMMIT();

    float oacc[8][4];
    #pragma unroll
    for (int i = 0; i < 8; i++)
        #pragma unroll
        for (int r = 0; r < 4; r++) oacc[i][r] = 0.f;
    float m0 = -1e30f, m1 = -1e30f, l0 = 0.f, l1 = 0.f;

    const uint32_t qa = sbase + (uint32_t)((wid * 16 + (lane & 15)) * APITCH
                                           + (lane >> 4) * 16);
    const uint32_t ka_l = (uint32_t)(((lane & 7) + ((lane >> 4) << 3)) * APITCH
                                           + ((lane >> 3) & 1) * 16);
    const uint32_t va_l = (uint32_t)((lane & 15) * APITCH + (lane >> 4) * 16);

    const int ntiles = 2 * qb + 2;

    #pragma unroll 1
    for (int t = 0; t < ntiles; t++) {
        const int k0 = t * 64;
        const uint32_t kvb = sbase + KV0 + (uint32_t)(t & 1) * KVBUF;

        if (t + 1 < ntiles) {
            attn_stage_kv(sbase + KV0 + (uint32_t)((t + 1) & 1) * KVBUF,
                          tid, Kh, Kl, Vh, Vl, base, (t + 1) * 64);
            CP_COMMIT();
            CP_WAIT(1);
        } else {
            CP_WAIT(0);
        }
        __syncthreads();

        const bool active = (k0 <= qbase + 15);
        if (active) {
            // ---- S = Q @ K^T (3-term split) ----
            float sacc[8][4];
            #pragma unroll
            for (int i = 0; i < 8; i++)
                #pragma unroll
                for (int r = 0; r < 4; r++) sacc[i][r] = 0.f;

            const uint32_t ka = kvb + ka_l;
            #pragma unroll
            for (int kk = 0; kk < 4; kk++) {
                const uint32_t ko = (uint32_t)(kk * 32);
                uint32_t ah[4], al[4];
                LDSM_X4(ah[0], ah[1], ah[2], ah[3], qa + ko);
                LDSM_X4(al[0], al[1], al[2], al[3], qa + ko + SQL);
                #pragma unroll
                for (int nt = 0; nt < 4; nt++) {
                    uint32_t ba = ka + ko + (uint32_t)(nt * 16 * APITCH);
                    uint32_t kh[4], kl[4];
                    LDSM_X4(kh[0], kh[1], kh[2], kh[3], ba);
                    LDSM_X4(kl[0], kl[1], kl[2], kl[3], ba + KVMAT);
                    MMA16816(sacc[2*nt],   ah, kh[0], kh[1]);
                    MMA16816(sacc[2*nt],   ah, kl[0], kl[1]);
                    MMA16816(sacc[2*nt],   al, kh[0], kh[1]);
                    MMA16816(sacc[2*nt+1], ah, kh[2], kh[3]);
                    MMA16816(sacc[2*nt+1], ah, kl[2], kl[3]);
                    MMA16816(sacc[2*nt+1], al, kh[2], kh[3]);
                }
            }

            // ---- causal mask ----
            if (t + 2 >= ntiles) {
                const int qi0 = qbase + g;
                const int qi1 = qbase + g + 8;
                #pragma unroll
                for (int dn = 0; dn < 8; dn++) {
                    const int kc = k0 + dn * 8 + tg * 2;
                    if (kc     > qi0) sacc[dn][0] = -1e30f;
                    if (kc + 1 > qi0) sacc[dn][1] = -1e30f;
                    if (kc     > qi1) sacc[dn][2] = -1e30f;
                    if (kc + 1 > qi1) sacc[dn][3] = -1e30f;
                }
            }

            // ---- online softmax ----
            float r0 = -1e30f, r1 = -1e30f;
            #pragma unroll
            for (int dn = 0; dn < 8; dn++) {
                r0 = fmaxf(r0, fmaxf(sacc[dn][0], sacc[dn][1]));
                r1 = fmaxf(r1, fmaxf(sacc[dn][2], sacc[dn][3]));
            }
            r0 = fmaxf(r0, __shfl_xor_sync(0xFFFFFFFFu, r0, 1));
            r0 = fmaxf(r0, __shfl_xor_sync(0xFFFFFFFFu, r0, 2));
            r1 = fmaxf(r1, __shfl_xor_sync(0xFFFFFFFFu, r1, 1));
            r1 = fmaxf(r1, __shfl_xor_sync(0xFFFFFFFFu, r1, 2));
            const float nm0 = fmaxf(m0, r0), nm1 = fmaxf(m1, r1);
            const float c0 = __expf(m0 - nm0), c1 = __expf(m1 - nm1);
            m0 = nm0; m1 = nm1;
            l0 *= c0;  l1 *= c1;
            #pragma unroll
            for (int dn = 0; dn < 8; dn++) {
                oacc[dn][0] *= c0; oacc[dn][1] *= c0;
                oacc[dn][2] *= c1; oacc[dn][3] *= c1;
            }
            #pragma unroll
            for (int dn = 0; dn < 8; dn++) {
                float p0 = __expf(sacc[dn][0] - m0);
                float p1 = __expf(sacc[dn][1] - m0);
                float p2 = __expf(sacc[dn][2] - m1);
                float p3 = __expf(sacc[dn][3] - m1);
                sacc[dn][0] = p0; sacc[dn][1] = p1;
                sacc[dn][2] = p2; sacc[dn][3] = p3;
                l0 += p0 + p1; l1 += p2 + p3;
            }

            // ---- O += P @ V (3-term split) ----
            const uint32_t va = kvb + 2 * KVMAT + va_l;
            #pragma unroll
            for (int kk = 0; kk < 4; kk++) {
                uint32_t ph[4], pl[4];
                split2(sacc[2*kk][0],   sacc[2*kk][1],   ph[0], pl[0]);
                split2(sacc[2*kk][2],   sacc[2*kk][3],   ph[1], pl[1]);
                split2(sacc[2*kk+1][0], sacc[2*kk+1][1], ph[2], pl[2]);
                split2(sacc[2*kk+1][2], sacc[2*kk+1][3], ph[3], pl[3]);
                #pragma unroll
                for (int dn = 0; dn < 4; dn++) {
                    uint32_t a = va + (uint32_t)(kk * 16 * APITCH + dn * 32);
                    uint32_t vh[4], vl[4];
                    LDSM_X4_T(vh[0], vh[1], vh[2], vh[3], a);
                    LDSM_X4_T(vl[0], vl[1], vl[2], vl[3], a + KVMAT);
                    MMA16816(oacc[2*dn],   ph, vh[0], vh[1]);
                    MMA16816(oacc[2*dn],   ph, vl[0], vl[1]);
                    MMA16816(oacc[2*dn],   pl, vh[0], vh[1]);
                    MMA16816(oacc[2*dn+1], ph, vh[2], vh[3]);
                    MMA16816(oacc[2*dn+1], ph, vl[2], vl[3]);
                    MMA16816(oacc[2*dn+1], pl, vh[2], vh[3]);
                }
            }
        }
        __syncthreads();
    }

    // ---- epilogue: normalize, split, store ----
    l0 += __shfl_xor_sync(0xFFFFFFFFu, l0, 1);
    l0 += __shfl_xor_sync(0xFFFFFFFFu, l0, 2);
    l1 += __shfl_xor_sync(0xFFFFFFFFu, l1, 1);
    l1 += __shfl_xor_sync(0xFFFFFFFFu, l1, 2);
    const float inv0 = 1.f / l0, inv1 = 1.f / l1;

    const size_t o0 = base + (size_t)(qbase + g) * D_MODEL + tg * 2;
    const size_t o1 = o0 + 8 * D_MODEL;
    #pragma unroll
    for (int dn = 0; dn < 8; dn++) {
        uint32_t h, l;
        split2(oacc[dn][0] * inv0, oacc[dn][1] * inv0, h, l);
        *(uint32_t*)(Oh + o0 + dn * 8) = h;
        *(uint32_t*)(Ol + o0 + dn * 8) = l;
        split2(oacc[dn][2] * inv1, oacc[dn][3] * inv1, h, l);
        *(uint32_t*)(Oh + o1 + dn * 8) = h;
        *(uint32_t*)(Ol + o1 + dn * 8) = l;
    }
}

// ======================================================================
extern "C" void kernel_launch(void* const* d_in, const int* in_sizes, int n_in,
                              void* d_out, int out_size)
{
    const float* x   = (const float*)d_in[0];
    const float* w_q = (const float*)d_in[1];
    const float* w_k = (const float*)d_in[2];
    const float* w_v = (const float*)d_in[3];
    const float* w_o = (const float*)d_in[4];
    const float* b_o = (const float*)d_in[5];
    float* out = (float*)d_out;

    __nv_bfloat16 *xh, *xl, *qh, *ql, *kh, *kl, *vh, *vl, *aoh, *aol, *wh, *wl;
    cudaGetSymbolAddress((void**)&xh,  g_xh);
    cudaGetSymbolAddress((void**)&xl,  g_xl);
    cudaGetSymbolAddress((void**)&qh,  g_qh);
    cudaGetSymbolAddress((void**)&ql,  g_ql);
    cudaGetSymbolAddress((void**)&kh,  g_kh);
    cudaGetSymbolAddress((void**)&kl,  g_kl);
    cudaGetSymbolAddress((void**)&vh,  g_vh);
    cudaGetSymbolAddress((void**)&vl,  g_vl);
    cudaGetSymbolAddress((void**)&aoh, g_aoh);
    cudaGetSymbolAddress((void**)&aol, g_aol);
    cudaGetSymbolAddress((void**)&wh,  g_wh);
    cudaGetSymbolAddress((void**)&wl,  g_wl);

    cudaFuncSetAttribute(qkv_mma,   cudaFuncAttributeMaxDynamicSharedMemorySize, GSMEM);
    cudaFuncSetAttribute(oproj_mma, cudaFuncAttributeMaxDynamicSharedMemorySize, GSMEM);
    cudaFuncSetAttribute(attn_mma,  cudaFuncAttributeMaxDynamicSharedMemorySize, ASMEM);

    const size_t WN = (size_t)D_MODEL * D_MODEL;

    presplit_all<<<MROWS + 4 * (int)(WN / 1024), 256>>>(
        x, w_q, w_k, w_v, w_o, xh, xl, wh, wl);

    dim3 qgrid(D_MODEL / 128, MROWS / 128, 3);   // (8, 64, 3)
    qkv_mma<<<qgrid, 256, GSMEM>>>(xh, xl, wh, wl, qh, ql, kh, kl, vh, vl);

    dim3 agrid(SEQ / 128, BATCH * NHEADS);       // (16, 64)
    attn_mma<<<agrid, 256, ASMEM>>>(qh, ql, kh, kl, vh, vl, aoh, aol);

    dim3 ogrid(D_MODEL / 128, MROWS / 128);      // (8, 64)
    oproj_mma<<<ogrid, 256, GSMEM>>>(aoh, aol, wh + 3 * WN, wl + 3 * WN, b_o, out);
}

// round 16
// speedup vs baseline: 1.1756x; 1.0153x over previous
#include <cuda_runtime.h>
#include <cuda_bf16.h>
#include <cstdint>

#define D_MODEL 1024
#define NHEADS  16
#define DK      64
#define BATCH   4
#define SEQ     2048
#define MROWS   (BATCH * SEQ)   // 8192

// -------- scratch (no allocations allowed; __device__ globals) --------
__device__ __nv_bfloat16 g_xh [MROWS * D_MODEL];
__device__ __nv_bfloat16 g_xl [MROWS * D_MODEL];
__device__ __nv_bfloat16 g_qh [MROWS * D_MODEL];
__device__ __nv_bfloat16 g_ql [MROWS * D_MODEL];
__device__ __nv_bfloat16 g_kh [MROWS * D_MODEL];
__device__ __nv_bfloat16 g_kl [MROWS * D_MODEL];
__device__ __nv_bfloat16 g_vh [MROWS * D_MODEL];
__device__ __nv_bfloat16 g_vl [MROWS * D_MODEL];
__device__ __nv_bfloat16 g_aoh[MROWS * D_MODEL];
__device__ __nv_bfloat16 g_aol[MROWS * D_MODEL];
__device__ __nv_bfloat16 g_wh [4][D_MODEL * D_MODEL];
__device__ __nv_bfloat16 g_wl [4][D_MODEL * D_MODEL];

// ======================================================================
// helpers
// ======================================================================
__device__ __forceinline__ uint32_t smem_u32(const void* p) {
    uint32_t a;
    asm("{ .reg .u64 t; cvta.to.shared.u64 t, %1; cvt.u32.u64 %0, t; }"
        : "=r"(a) : "l"(p));
    return a;
}

#define LDSM_X4(r0, r1, r2, r3, addr)                                         \
    asm volatile("ldmatrix.sync.aligned.m8n8.x4.shared.b16 {%0,%1,%2,%3}, [%4];" \
                 : "=r"(r0), "=r"(r1), "=r"(r2), "=r"(r3) : "r"(addr))

#define LDSM_X4_T(r0, r1, r2, r3, addr)                                       \
    asm volatile("ldmatrix.sync.aligned.m8n8.x4.trans.shared.b16 {%0,%1,%2,%3}, [%4];" \
                 : "=r"(r0), "=r"(r1), "=r"(r2), "=r"(r3) : "r"(addr))

#define MMA16816(d, a, b0v, b1v)                                              \
    asm volatile("mma.sync.aligned.m16n8k16.row.col.f32.bf16.bf16.f32 "       \
                 "{%0,%1,%2,%3}, {%4,%5,%6,%7}, {%8,%9}, {%0,%1,%2,%3};"      \
                 : "+f"((d)[0]), "+f"((d)[1]), "+f"((d)[2]), "+f"((d)[3])     \
                 : "r"((a)[0]), "r"((a)[1]), "r"((a)[2]), "r"((a)[3]),        \
                   "r"(b0v), "r"(b1v))

#define CP_ASYNC16(saddr, gptr)                                               \
    asm volatile("cp.async.cg.shared.global [%0], [%1], 16;"                  \
                 :: "r"(saddr), "l"(gptr))
#define CP_COMMIT() asm volatile("cp.async.commit_group;" ::: "memory")
#define CP_WAIT(n)  asm volatile("cp.async.wait_group %0;" :: "n"(n) : "memory")

// split one float pair into bf16 hi + bf16 lo packed u32s
__device__ __forceinline__ void split2(float x, float y, uint32_t& hi, uint32_t& lo) {
    __nv_bfloat162 h = __floats2bfloat162_rn(x, y);
    float2 f = __bfloat1622float2(h);
    __nv_bfloat162 l = __floats2bfloat162_rn(x - f.x, y - f.y);
    hi = *reinterpret_cast<uint32_t*>(&h);
    lo = *reinterpret_cast<uint32_t*>(&l);
}

// ======================================================================
// fused presplit: x + 4 weights in ONE launch. 1024 elems per block.
// ======================================================================
__global__ __launch_bounds__(256)
void presplit_all(const float* __restrict__ x,
                  const float* __restrict__ wq, const float* __restrict__ wk,
                  const float* __restrict__ wv, const float* __restrict__ wo,
                  __nv_bfloat16* __restrict__ xh, __nv_bfloat16* __restrict__ xl,
                  __nv_bfloat16* __restrict__ wh, __nv_bfloat16* __restrict__ wl)
{
    const int b = blockIdx.x;
    const size_t WN = (size_t)D_MODEL * D_MODEL;
    const float* in;
    __nv_bfloat16 *hi, *lo;
    size_t eo;
    if (b < MROWS) {
        in = x; hi = xh; lo = xl;
        eo = (size_t)b * 1024;
    } else {
        const int r = b - MROWS;
        const int w = r >> 10;
        in = (w == 0) ? wq : (w == 1) ? wk : (w == 2) ? wv : wo;
        hi = wh + (size_t)w * WN;
        lo = wl + (size_t)w * WN;
        eo = (size_t)(r & 1023) * 1024;
    }
    const size_t i = eo + (size_t)threadIdx.x * 4;
    float4 v = *(const float4*)(in + i);
    uint2 h, l;
    split2(v.x, v.y, h.x, l.x);
    split2(v.z, v.w, h.y, l.y);
    *(uint2*)(hi + i) = h;
    *(uint2*)(lo + i) = l;
}

// ======================================================================
// GEMM mainloop: C = A @ B^T, bf16x3, rolling-prefetch micro-steps.
// 80 KB smem -> 2 CTAs/SM.
// ======================================================================
#define GPITCH 80
#define GBK    32
#define GNIT   (D_MODEL / GBK)
#define MAT_B  (128 * GPITCH)          // 10240
#define BUF_B  (4 * MAT_B)             // 40960
#define GSMEM  (2 * BUF_B)             // 81920

__device__ __forceinline__ void gemm_stage(
    uint32_t sbase, uint32_t bufo, int tid, int koff,
    const __nv_bfloat16* Ah, const __nv_bfloat16* Al,
    const __nv_bfloat16* Bh, const __nv_bfloat16* Bl,
    int bm, int bn)
{
    #pragma unroll
    for (int i = 0; i < 2; i++) {
        const int id  = tid + 256 * i;      // 0..511
        const int row = id >> 2;
        const int c16 = id & 3;
        const uint32_t so = sbase + bufo + (uint32_t)(row * GPITCH + c16 * 16);
        const size_t ga = (size_t)(bm + row) * D_MODEL + koff + c16 * 8;
        const size_t gb = (size_t)(bn + row) * D_MODEL + koff + c16 * 8;
        CP_ASYNC16(so,             Ah + ga);
        CP_ASYNC16(so + MAT_B,     Al + ga);
        CP_ASYNC16(so + 2 * MAT_B, Bh + gb);
        CP_ASYNC16(so + 3 * MAT_B, Bl + gb);
    }
}

__device__ __forceinline__ void gemm_load_a(uint32_t* fa, int ks, uint32_t base) {
    #pragma unroll
    for (int im = 0; im < 2; im++) {
        uint32_t aa = base + (uint32_t)(ks * 32 + im * 16 * GPITCH);
        LDSM_X4(fa[im*8+0], fa[im*8+1], fa[im*8+2], fa[im*8+3], aa);
        LDSM_X4(fa[im*8+4], fa[im*8+5], fa[im*8+6], fa[im*8+7], aa + MAT_B);
    }
}
__device__ __forceinline__ void gemm_load_b(uint32_t* fb, int ks, int nt, uint32_t base) {
    uint32_t ba = base + (uint32_t)(ks * 32 + nt * 16 * GPITCH);
    LDSM_X4(fb[0], fb[1], fb[2], fb[3], ba);
    LDSM_X4(fb[4], fb[5], fb[6], fb[7], ba + MAT_B);
}

__device__ __forceinline__ void gemm_mainloop(
    const __nv_bfloat16* __restrict__ Ah, const __nv_bfloat16* __restrict__ Al,
    const __nv_bfloat16* __restrict__ Bh, const __nv_bfloat16* __restrict__ Bl,
    int bm, int bn, uint32_t sbase, int tid, float (&acc)[2][8][4])
{
    const int lane   = tid & 31;
    const int wid    = tid >> 5;
    const int warp_m = wid & 3;
    const int warp_n = wid >> 2;

    const uint32_t a_l = sbase + (uint32_t)((warp_m * 32 + (lane & 15)) * GPITCH
                                            + (lane >> 4) * 16);
    const int bnl = warp_n * 64 + (lane & 7) + ((lane >> 4) << 3);
    const uint32_t b_l = sbase + 2 * MAT_B + (uint32_t)(bnl * GPITCH
                                            + ((lane >> 3) & 1) * 16);

    gemm_stage(sbase, 0, tid, 0, Ah, Al, Bh, Bl, bm, bn);
    CP_COMMIT();

    #pragma unroll 1
    for (int it = 0; it < GNIT; it++) {
        const uint32_t bufo = (uint32_t)(it & 1) * BUF_B;
        if (it + 1 < GNIT) {
            gemm_stage(sbase, (uint32_t)((it + 1) & 1) * BUF_B, tid,
                       (it + 1) * GBK, Ah, Al, Bh, Bl, bm, bn);
            CP_COMMIT();
            CP_WAIT(1);
        } else {
            CP_WAIT(0);
        }
        __syncthreads();

        // rolling-prefetch micro-steps: 8 steps (ks 0..1 x nt 0..3),
        // each issues next step's B LDSMs (and ks=1 A LDSMs at s==3)
        // before its own 12 MMAs -> continuous tensor issue.
        uint32_t fa[2][16], fb[2][8];
        gemm_load_a(fa[0], 0, a_l + bufo);
        gemm_load_b(fb[0], 0, 0, b_l + bufo);

        #pragma unroll
        for (int s = 0; s < 8; s++) {
            const int nt = s & 3;
            const int ab = s >> 2;          // A buffer for this step
            const int bb = s & 1;           // B buffer for this step
            if (s < 7)
                gemm_load_b(fb[bb ^ 1], (s + 1) >> 2, (s + 1) & 3, b_l + bufo);
            if (s == 3)
                gemm_load_a(fa[1], 1, a_l + bufo);

            // 12 MMAs, term-major (4 independent per term)
            MMA16816(acc[0][2*nt],   &fa[ab][0],  fb[bb][0], fb[bb][1]);
            MMA16816(acc[0][2*nt+1], &fa[ab][0],  fb[bb][2], fb[bb][3]);
            MMA16816(acc[1][2*nt],   &fa[ab][8],  fb[bb][0], fb[bb][1]);
            MMA16816(acc[1][2*nt+1], &fa[ab][8],  fb[bb][2], fb[bb][3]);
            MMA16816(acc[0][2*nt],   &fa[ab][0],  fb[bb][4], fb[bb][5]);
            MMA16816(acc[0][2*nt+1], &fa[ab][0],  fb[bb][6], fb[bb][7]);
            MMA16816(acc[1][2*nt],   &fa[ab][8],  fb[bb][4], fb[bb][5]);
            MMA16816(acc[1][2*nt+1], &fa[ab][8],  fb[bb][6], fb[bb][7]);
            MMA16816(acc[0][2*nt],   &fa[ab][4],  fb[bb][0], fb[bb][1]);
            MMA16816(acc[0][2*nt+1], &fa[ab][4],  fb[bb][2], fb[bb][3]);
            MMA16816(acc[1][2*nt],   &fa[ab][12], fb[bb][0], fb[bb][1]);
            MMA16816(acc[1][2*nt+1], &fa[ab][12], fb[bb][2], fb[bb][3]);
        }
        __syncthreads();
    }
}

// ---- fused QKV projection: gridDim.z selects weight + destination ----
__global__ __launch_bounds__(256, 2)
void qkv_mma(const __nv_bfloat16* __restrict__ xh,
             const __nv_bfloat16* __restrict__ xl,
             const __nv_bfloat16* __restrict__ wh,
             const __nv_bfloat16* __restrict__ wl,
             __nv_bfloat16* __restrict__ qh, __nv_bfloat16* __restrict__ ql,
             __nv_bfloat16* __restrict__ kh, __nv_bfloat16* __restrict__ kl,
             __nv_bfloat16* __restrict__ vh, __nv_bfloat16* __restrict__ vl)
{
    extern __shared__ char sm[];
    const uint32_t sbase = smem_u32(sm);
    const int tid = threadIdx.x;
    const int z   = blockIdx.z;
    const int bm  = blockIdx.y * 128;
    const int bn  = blockIdx.x * 128;
    const size_t WN = (size_t)D_MODEL * D_MODEL;

    float acc[2][8][4];
    #pragma unroll
    for (int i = 0; i < 2; i++)
        #pragma unroll
        for (int j = 0; j < 8; j++)
            #pragma unroll
            for (int r = 0; r < 4; r++) acc[i][j][r] = 0.f;

    gemm_mainloop(xh, xl, wh + (size_t)z * WN, wl + (size_t)z * WN,
                  bm, bn, sbase, tid, acc);

    __nv_bfloat16* Ch = (z == 0) ? qh : (z == 1) ? kh : vh;
    __nv_bfloat16* Cl = (z == 0) ? ql : (z == 1) ? kl : vl;
    const float s = (z == 0) ? 0.125f : 1.f;

    const int lane = tid & 31;
    const int wid  = tid >> 5;
    const int g    = lane >> 2;
    const int q4   = (lane & 3) * 2;
    #pragma unroll
    for (int im = 0; im < 2; im++) {
        const int r0 = bm + (wid & 3) * 32 + im * 16 + g;
        #pragma unroll
        for (int in = 0; in < 8; in++) {
            const int c = bn + (wid >> 2) * 64 + in * 8 + q4;
            uint32_t h, l;
            split2(acc[im][in][0] * s, acc[im][in][1] * s, h, l);
            *(uint32_t*)(Ch + (size_t)r0 * D_MODEL + c) = h;
            *(uint32_t*)(Cl + (size_t)r0 * D_MODEL + c) = l;
            split2(acc[im][in][2] * s, acc[im][in][3] * s, h, l);
            *(uint32_t*)(Ch + (size_t)(r0 + 8) * D_MODEL + c) = h;
            *(uint32_t*)(Cl + (size_t)(r0 + 8) * D_MODEL + c) = l;
        }
    }
}

// ---- output projection: fp32 out + bias ----
__global__ __launch_bounds__(256, 2)
void oproj_mma(const __nv_bfloat16* __restrict__ Ah,
               const __nv_bfloat16* __restrict__ Al,
               const __nv_bfloat16* __restrict__ Bh,
               const __nv_bfloat16* __restrict__ Bl,
               const float* __restrict__ bias,
               float* __restrict__ C)
{
    extern __shared__ char sm[];
    const uint32_t sbase = smem_u32(sm);
    const int tid = threadIdx.x;
    const int bm  = blockIdx.y * 128;
    const int bn  = blockIdx.x * 128;

    float acc[2][8][4];
    #pragma unroll
    for (int i = 0; i < 2; i++)
        #pragma unroll
        for (int j = 0; j < 8; j++)
            #pragma unroll
            for (int r = 0; r < 4; r++) acc[i][j][r] = 0.f;

    gemm_mainloop(Ah, Al, Bh, Bl, bm, bn, sbase, tid, acc);

    const int lane = tid & 31;
    const int wid  = tid >> 5;
    const int g    = lane >> 2;
    const int q4   = (lane & 3) * 2;
    #pragma unroll
    for (int im = 0; im < 2; im++) {
        const int r0 = bm + (wid & 3) * 32 + im * 16 + g;
        #pragma unroll
        for (int in = 0; in < 8; in++) {
            const int c = bn + (wid >> 2) * 64 + in * 8 + q4;
            const float b0 = bias[c], b1 = bias[c + 1];
            *(float2*)(C + (size_t)r0 * D_MODEL + c) =
                make_float2(acc[im][in][0] + b0, acc[im][in][1] + b1);
            *(float2*)(C + (size_t)(r0 + 8) * D_MODEL + c) =
                make_float2(acc[im][in][2] + b0, acc[im][in][3] + b1);
        }
    }
}

// ======================================================================
// Tensor-core causal flash attention (dep-distance-2 MMA order).
// ======================================================================
#define APITCH 144
#define SQL   (128 * APITCH)            // 18432
#define KV0   (2 * 128 * APITCH)        // 36864
#define KVMAT (64 * APITCH)             // 9216
#define KVBUF (4 * KVMAT)               // 36864
#define ASMEM (KV0 + 2 * KVBUF)         // 110592

__device__ __forceinline__ void attn_stage_kv(
    uint32_t dst, int tid, const __nv_bfloat16* Kh, const __nv_bfloat16* Kl,
    const __nv_bfloat16* Vh, const __nv_bfloat16* Vl,
    size_t gbase, int k0)
{
    #pragma unroll
    for (int i = 0; i < 2; i++) {
        const int id  = tid + 256 * i;        // 0..511
        const int row = id >> 3;              // 0..63
        const int c16 = id & 7;
        const uint32_t so = dst + (uint32_t)(row * APITCH + c16 * 16);
        const size_t gk = gbase + (size_t)(k0 + row) * D_MODEL + c16 * 8;
        CP_ASYNC16(so,             Kh + gk);
        CP_ASYNC16(so + KVMAT,     Kl + gk);
        CP_ASYNC16(so + 2 * KVMAT, Vh + gk);
        CP_ASYNC16(so + 3 * KVMAT, Vl + gk);
    }
}

__global__ __launch_bounds__(256, 2)
void attn_mma(const __nv_bfloat16* __restrict__ Qh,
              const __nv_bfloat16* __restrict__ Ql,
              const __nv_bfloat16* __restrict__ Kh,
              const __nv_bfloat16* __restrict__ Kl,
              const __nv_bfloat16* __restrict__ Vh,
              const __nv_bfloat16* __restrict__ Vl,
              __nv_bfloat16* __restrict__ Oh,
              __nv_bfloat16* __restrict__ Ol)
{
    extern __shared__ char sm[];
    const uint32_t sbase = smem_u32(sm);

    const int tid  = threadIdx.x;
    const int lane = tid & 31;
    const int wid  = tid >> 5;
    const int g    = lane >> 2;
    const int tg   = lane & 3;
    const int qb   = gridDim.x - 1 - blockIdx.x;   // heavy blocks first
    const int bh   = blockIdx.y;
    const size_t base = (size_t)(bh >> 4) * SEQ * D_MODEL + (size_t)(bh & 15) * DK;

    const int qbase = qb * 128 + wid * 16;

    // ---- stage Q (cp.async, once) ----
    #pragma unroll
    for (int i = 0; i < 4; i++) {
        const int id  = tid + 256 * i;
        const int row = id >> 3;
        const int c16 = id & 7;
        const uint32_t so = sbase + (uint32_t)(row * APITCH + c16 * 16);
        const size_t gq = base + (size_t)(qb * 128 + row) * D_MODEL + c16 * 8;
        CP_ASYNC16(so,       Qh + gq);
        CP_ASYNC16(so + SQL, Ql + gq);
    }
    attn_stage_kv(sbase + KV0, tid, Kh, Kl, Vh, Vl, base, 0);
    CP_COMMIT();

    float oacc[8][4];
    #pragma unroll
    for (int i = 0; i < 8; i++)
        #pragma unroll
        for (int r = 0; r < 4; r++) oacc[i][r] = 0.f;
    float m0 = -1e30f, m1 = -1e30f, l0 = 0.f, l1 = 0.f;

    const uint32_t qa = sbase + (uint32_t)((wid * 16 + (lane & 15)) * APITCH
                                           + (lane >> 4) * 16);
    const uint32_t ka_l = (uint32_t)(((lane & 7) + ((lane >> 4) << 3)) * APITCH
                                           + ((lane >> 3) & 1) * 16);
    const uint32_t va_l = (uint32_t)((lane & 15) * APITCH + (lane >> 4) * 16);

    const int ntiles = 2 * qb + 2;

    #pragma unroll 1
    for (int t = 0; t < ntiles; t++) {
        const int k0 = t * 64;
        const uint32_t kvb = sbase + KV0 + (uint32_t)(t & 1) * KVBUF;

        if (t + 1 < ntiles) {
            attn_stage_kv(sbase + KV0 + (uint32_t)((t + 1) & 1) * KVBUF,
                          tid, Kh, Kl, Vh, Vl, base, (t + 1) * 64);
            CP_COMMIT();
            CP_WAIT(1);
        } else {
            CP_WAIT(0);
        }
        __syncthreads();

        const bool active = (k0 <= qbase + 15);
        if (active) {
            // ---- S = Q @ K^T (3-term split) ----
            float sacc[8][4];
            #pragma unroll
            for (int i = 0; i < 8; i++)
                #pragma unroll
                for (int r = 0; r < 4; r++) sacc[i][r] = 0.f;

            const uint32_t ka = kvb + ka_l;
            #pragma unroll
            for (int kk = 0; kk < 4; kk++) {
                const uint32_t ko = (uint32_t)(kk * 32);
                uint32_t ah[4], al[4];
                LDSM_X4(ah[0], ah[1], ah[2], ah[3], qa + ko);
                LDSM_X4(al[0], al[1], al[2], al[3], qa + ko + SQL);
                #pragma unroll
                for (int nt = 0; nt < 4; nt++) {
                    uint32_t ba = ka + ko + (uint32_t)(nt * 16 * APITCH);
                    uint32_t kh[4], kl[4];
                    LDSM_X4(kh[0], kh[1], kh[2], kh[3], ba);
                    LDSM_X4(kl[0], kl[1], kl[2], kl[3], ba + KVMAT);
                    MMA16816(sacc[2*nt],   ah, kh[0], kh[1]);
                    MMA16816(sacc[2*nt+1], ah, kh[2], kh[3]);
                    MMA16816(sacc[2*nt],   ah, kl[0], kl[1]);
                    MMA16816(sacc[2*nt+1], ah, kl[2], kl[3]);
                    MMA16816(sacc[2*nt],   al, kh[0], kh[1]);
                    MMA16816(sacc[2*nt+1], al, kh[2], kh[3]);
                }
            }

            // ---- causal mask ----
            if (t + 2 >= ntiles) {
                const int qi0 = qbase + g;
                const int qi1 = qbase + g + 8;
                #pragma unroll
                for (int dn = 0; dn < 8; dn++) {
                    const int kc = k0 + dn * 8 + tg * 2;
                    if (kc     > qi0) sacc[dn][0] = -1e30f;
                    if (kc + 1 > qi0) sacc[dn][1] = -1e30f;
                    if (kc     > qi1) sacc[dn][2] = -1e30f;
                    if (kc + 1 > qi1) sacc[dn][3] = -1e30f;
                }
            }

            // ---- online softmax ----
            float r0 = -1e30f, r1 = -1e30f;
            #pragma unroll
            for (int dn = 0; dn < 8; dn++) {
                r0 = fmaxf(r0, fmaxf(sacc[dn][0], sacc[dn][1]));
                r1 = fmaxf(r1, fmaxf(sacc[dn][2], sacc[dn][3]));
            }
            r0 = fmaxf(r0, __shfl_xor_sync(0xFFFFFFFFu, r0, 1));
            r0 = fmaxf(r0, __shfl_xor_sync(0xFFFFFFFFu, r0, 2));
            r1 = fmaxf(r1, __shfl_xor_sync(0xFFFFFFFFu, r1, 1));
            r1 = fmaxf(r1, __shfl_xor_sync(0xFFFFFFFFu, r1, 2));
            const float nm0 = fmaxf(m0, r0), nm1 = fmaxf(m1, r1);
            const float c0 = __expf(m0 - nm0), c1 = __expf(m1 - nm1);
            m0 = nm0; m1 = nm1;
            l0 *= c0;  l1 *= c1;
            #pragma unroll
            for (int dn = 0; dn < 8; dn++) {
                oacc[dn][0] *= c0; oacc[dn][1] *= c0;
                oacc[dn][2] *= c1; oacc[dn][3] *= c1;
            }
            #pragma unroll
            for (int dn = 0; dn < 8; dn++) {
                float p0 = __expf(sacc[dn][0] - m0);
                float p1 = __expf(sacc[dn][1] - m0);
                float p2 = __expf(sacc[dn][2] - m1);
                float p3 = __expf(sacc[dn][3] - m1);
                sacc[dn][0] = p0; sacc[dn][1] = p1;
                sacc[dn][2] = p2; sacc[dn][3] = p3;
                l0 += p0 + p1; l1 += p2 + p3;
            }

            // ---- O += P @ V (3-term split) ----
            const uint32_t va = kvb + 2 * KVMAT + va_l;
            #pragma unroll
            for (int kk = 0; kk < 4; kk++) {
                uint32_t ph[4], pl[4];
                split2(sacc[2*kk][0],   sacc[2*kk][1],   ph[0], pl[0]);
                split2(sacc[2*kk][2],   sacc[2*kk][3],   ph[1], pl[1]);
                split2(sacc[2*kk+1][0], sacc[2*kk+1][1], ph[2], pl[2]);
                split2(sacc[2*kk+1][2], sacc[2*kk+1][3], ph[3], pl[3]);
                #pragma unroll
                for (int dn = 0; dn < 4; dn++) {
                    uint32_t a = va + (uint32_t)(kk * 16 * APITCH + dn * 32);
                    uint32_t vh[4], vl[4];
                    LDSM_X4_T(vh[0], vh[1], vh[2], vh[3], a);
                    LDSM_X4_T(vl[0], vl[1], vl[2], vl[3], a + KVMAT);
                    MMA16816(oacc[2*dn],   ph, vh[0], vh[1]);
                    MMA16816(oacc[2*dn+1], ph, vh[2], vh[3]);
                    MMA16816(oacc[2*dn],   ph, vl[0], vl[1]);
                    MMA16816(oacc[2*dn+1], ph, vl[2], vl[3]);
                    MMA16816(oacc[2*dn],   pl, vh[0], vh[1]);
                    MMA16816(oacc[2*dn+1], pl, vh[2], vh[3]);
                }
            }
        }
        __syncthreads();
    }

    // ---- epilogue: normalize, split, store ----
    l0 += __shfl_xor_sync(0xFFFFFFFFu, l0, 1);
    l0 += __shfl_xor_sync(0xFFFFFFFFu, l0, 2);
    l1 += __shfl_xor_sync(0xFFFFFFFFu, l1, 1);
    l1 += __shfl_xor_sync(0xFFFFFFFFu, l1, 2);
    const float inv0 = 1.f / l0, inv1 = 1.f / l1;

    const size_t o0 = base + (size_t)(qbase + g) * D_MODEL + tg * 2;
    const size_t o1 = o0 + 8 * D_MODEL;
    #pragma unroll
    for (int dn = 0; dn < 8; dn++) {
        uint32_t h, l;
        split2(oacc[dn][0] * inv0, oacc[dn][1] * inv0, h, l);
        *(uint32_t*)(Oh + o0 + dn * 8) = h;
        *(uint32_t*)(Ol + o0 + dn * 8) = l;
        split2(oacc[dn][2] * inv1, oacc[dn][3] * inv1, h, l);
        *(uint32_t*)(Oh + o1 + dn * 8) = h;
        *(uint32_t*)(Ol + o1 + dn * 8) = l;
    }
}

// ======================================================================
extern "C" void kernel_launch(void* const* d_in, const int* in_sizes, int n_in,
                              void* d_out, int out_size)
{
    const float* x   = (const float*)d_in[0];
    const float* w_q = (const float*)d_in[1];
    const float* w_k = (const float*)d_in[2];
    const float* w_v = (const float*)d_in[3];
    const float* w_o = (const float*)d_in[4];
    const float* b_o = (const float*)d_in[5];
    float* out = (float*)d_out;

    __nv_bfloat16 *xh, *xl, *qh, *ql, *kh, *kl, *vh, *vl, *aoh, *aol, *wh, *wl;
    cudaGetSymbolAddress((void**)&xh,  g_xh);
    cudaGetSymbolAddress((void**)&xl,  g_xl);
    cudaGetSymbolAddress((void**)&qh,  g_qh);
    cudaGetSymbolAddress((void**)&ql,  g_ql);
    cudaGetSymbolAddress((void**)&kh,  g_kh);
    cudaGetSymbolAddress((void**)&kl,  g_kl);
    cudaGetSymbolAddress((void**)&vh,  g_vh);
    cudaGetSymbolAddress((void**)&vl,  g_vl);
    cudaGetSymbolAddress((void**)&aoh, g_aoh);
    cudaGetSymbolAddress((void**)&aol, g_aol);
    cudaGetSymbolAddress((void**)&wh,  g_wh);
    cudaGetSymbolAddress((void**)&wl,  g_wl);

    cudaFuncSetAttribute(qkv_mma,   cudaFuncAttributeMaxDynamicSharedMemorySize, GSMEM);
    cudaFuncSetAttribute(oproj_mma, cudaFuncAttributeMaxDynamicSharedMemorySize, GSMEM);
    cudaFuncSetAttribute(attn_mma,  cudaFuncAttributeMaxDynamicSharedMemorySize, ASMEM);

    const size_t WN = (size_t)D_MODEL * D_MODEL;

    presplit_all<<<MROWS + 4 * (int)(WN / 1024), 256>>>(
        x, w_q, w_k, w_v, w_o, xh, xl, wh, wl);

    dim3 qgrid(D_MODEL / 128, MROWS / 128, 3);   // (8, 64, 3)
    qkv_mma<<<qgrid, 256, GSMEM>>>(xh, xl, wh, wl, qh, ql, kh, kl, vh, vl);

    dim3 agrid(SEQ / 128, BATCH * NHEADS);       // (16, 64)
    attn_mma<<<agrid, 256, ASMEM>>>(qh, ql, kh, kl, vh, vl, aoh, aol);

    dim3 ogrid(D_MODEL / 128, MROWS / 128);      // (8, 64)
    oproj_mma<<<ogrid, 256, GSMEM>>>(aoh, aol, wh + 3 * WN, wl + 3 * WN, b_o, out);
}

// round 17
// speedup vs baseline: 1.5879x; 1.3507x over previous
#include <cuda_runtime.h>
#include <cuda_fp16.h>
#include <cstdint>

#define D_MODEL 1024
#define NHEADS  16
#define DK      64
#define BATCH   4
#define SEQ     2048
#define MROWS   (BATCH * SEQ)   // 8192

// -------- scratch (no allocations allowed; __device__ globals) --------
// fp16 split: A-sides single (xh, qh, aoh); B-sides pair (w, k, v).
__device__ __half g_xh [MROWS * D_MODEL];
__device__ __half g_qh [MROWS * D_MODEL];
__device__ __half g_kh [MROWS * D_MODEL];
__device__ __half g_kl [MROWS * D_MODEL];
__device__ __half g_vh [MROWS * D_MODEL];
__device__ __half g_vl [MROWS * D_MODEL];
__device__ __half g_aoh[MROWS * D_MODEL];
__device__ __half g_wh [4][D_MODEL * D_MODEL];
__device__ __half g_wl [4][D_MODEL * D_MODEL];

// ======================================================================
// helpers
// ======================================================================
__device__ __forceinline__ uint32_t smem_u32(const void* p) {
    uint32_t a;
    asm("{ .reg .u64 t; cvta.to.shared.u64 t, %1; cvt.u32.u64 %0, t; }"
        : "=r"(a) : "l"(p));
    return a;
}

#define LDSM_X4(r0, r1, r2, r3, addr)                                         \
    asm volatile("ldmatrix.sync.aligned.m8n8.x4.shared.b16 {%0,%1,%2,%3}, [%4];" \
                 : "=r"(r0), "=r"(r1), "=r"(r2), "=r"(r3) : "r"(addr))

#define LDSM_X4_T(r0, r1, r2, r3, addr)                                       \
    asm volatile("ldmatrix.sync.aligned.m8n8.x4.trans.shared.b16 {%0,%1,%2,%3}, [%4];" \
                 : "=r"(r0), "=r"(r1), "=r"(r2), "=r"(r3) : "r"(addr))

#define MMA16816(d, a, b0v, b1v)                                              \
    asm volatile("mma.sync.aligned.m16n8k16.row.col.f32.f16.f16.f32 "         \
                 "{%0,%1,%2,%3}, {%4,%5,%6,%7}, {%8,%9}, {%0,%1,%2,%3};"      \
                 : "+f"((d)[0]), "+f"((d)[1]), "+f"((d)[2]), "+f"((d)[3])     \
                 : "r"((a)[0]), "r"((a)[1]), "r"((a)[2]), "r"((a)[3]),        \
                   "r"(b0v), "r"(b1v))

#define CP_ASYNC16(saddr, gptr)                                               \
    asm volatile("cp.async.cg.shared.global [%0], [%1], 16;"                  \
                 :: "r"(saddr), "l"(gptr))
#define CP_COMMIT() asm volatile("cp.async.commit_group;" ::: "memory")
#define CP_WAIT(n)  asm volatile("cp.async.wait_group %0;" :: "n"(n) : "memory")

// fp32 pair -> fp16 hi + fp16 lo (packed u32)
__device__ __forceinline__ void split2h(float x, float y, uint32_t& hi, uint32_t& lo) {
    __half2 h = __floats2half2_rn(x, y);
    float2 f = __half22float2(h);
    __half2 l = __floats2half2_rn(x - f.x, y - f.y);
    hi = *reinterpret_cast<uint32_t*>(&h);
    lo = *reinterpret_cast<uint32_t*>(&l);
}
// fp32 pair -> single fp16 (packed u32)
__device__ __forceinline__ uint32_t cvt2h(float x, float y) {
    __half2 h = __floats2half2_rn(x, y);
    return *reinterpret_cast<uint32_t*>(&h);
}

// ======================================================================
// fused presplit: x (single) + 4 weights (pair) in ONE launch.
// ======================================================================
__global__ __launch_bounds__(256)
void presplit_all(const float* __restrict__ x,
                  const float* __restrict__ wq, const float* __restrict__ wk,
                  const float* __restrict__ wv, const float* __restrict__ wo,
                  __half* __restrict__ xh,
                  __half* __restrict__ wh, __half* __restrict__ wl)
{
    const int b = blockIdx.x;
    const size_t WN = (size_t)D_MODEL * D_MODEL;
    if (b < MROWS) {
        const size_t i = (size_t)b * 1024 + (size_t)threadIdx.x * 4;
        float4 v = *(const float4*)(x + i);
        uint2 h;
        h.x = cvt2h(v.x, v.y);
        h.y = cvt2h(v.z, v.w);
        *(uint2*)(xh + i) = h;
    } else {
        const int r = b - MROWS;
        const int w = r >> 10;
        const float* in = (w == 0) ? wq : (w == 1) ? wk : (w == 2) ? wv : wo;
        const size_t i = (size_t)(r & 1023) * 1024 + (size_t)threadIdx.x * 4;
        float4 v = *(const float4*)(in + i);
        uint2 h, l;
        split2h(v.x, v.y, h.x, l.x);
        split2h(v.z, v.w, h.y, l.y);
        *(uint2*)(wh + (size_t)w * WN + i) = h;
        *(uint2*)(wl + (size_t)w * WN + i) = l;
    }
}

// ======================================================================
// GEMM mainloop: C = A @ B^T. A single fp16, B fp16 pair. 2 MMA terms.
// 3-stage cp.async pipeline, 92160 B smem -> 2 CTAs/SM.
// ======================================================================
#define GPITCH 80
#define GBK    32
#define GNIT   (D_MODEL / GBK)
#define MAT_B  (128 * GPITCH)          // 10240
#define STG_B  (3 * MAT_B)             // 30720 per stage (A, Bh, Bl)
#define GSMEM  (3 * STG_B)             // 92160

__device__ __forceinline__ void gemm_stage(
    uint32_t sbase, uint32_t bufo, int tid, int koff,
    const __half* Ah, const __half* Bh, const __half* Bl,
    int bm, int bn)
{
    #pragma unroll
    for (int i = 0; i < 2; i++) {
        const int id  = tid + 256 * i;      // 0..511
        const int row = id >> 2;
        const int c16 = id & 3;
        const uint32_t so = sbase + bufo + (uint32_t)(row * GPITCH + c16 * 16);
        const size_t ga = (size_t)(bm + row) * D_MODEL + koff + c16 * 8;
        const size_t gb = (size_t)(bn + row) * D_MODEL + koff + c16 * 8;
        CP_ASYNC16(so,             Ah + ga);
        CP_ASYNC16(so + MAT_B,     Bh + gb);
        CP_ASYNC16(so + 2 * MAT_B, Bl + gb);
    }
}

__device__ __forceinline__ void gemm_load_a(uint32_t* fa, int ks, uint32_t base) {
    #pragma unroll
    for (int im = 0; im < 2; im++) {
        uint32_t aa = base + (uint32_t)(ks * 32 + im * 16 * GPITCH);
        LDSM_X4(fa[im*4+0], fa[im*4+1], fa[im*4+2], fa[im*4+3], aa);
    }
}
__device__ __forceinline__ void gemm_load_b(uint32_t* fb, int ks, int nt, uint32_t base) {
    uint32_t ba = base + (uint32_t)(ks * 32 + nt * 16 * GPITCH);
    LDSM_X4(fb[0], fb[1], fb[2], fb[3], ba);            // Bh
    LDSM_X4(fb[4], fb[5], fb[6], fb[7], ba + MAT_B);    // Bl
}

__device__ __forceinline__ void gemm_mainloop(
    const __half* __restrict__ Ah,
    const __half* __restrict__ Bh, const __half* __restrict__ Bl,
    int bm, int bn, uint32_t sbase, int tid, float (&acc)[2][8][4])
{
    const int lane   = tid & 31;
    const int wid    = tid >> 5;
    const int warp_m = wid & 3;
    const int warp_n = wid >> 2;

    const uint32_t a_l = sbase + (uint32_t)((warp_m * 32 + (lane & 15)) * GPITCH
                                            + (lane >> 4) * 16);
    const int bnl = warp_n * 64 + (lane & 7) + ((lane >> 4) << 3);
    const uint32_t b_l = sbase + MAT_B + (uint32_t)(bnl * GPITCH
                                            + ((lane >> 3) & 1) * 16);

    gemm_stage(sbase, 0,         tid, 0,       Ah, Bh, Bl, bm, bn);
    CP_COMMIT();
    gemm_stage(sbase, STG_B,     tid, GBK,     Ah, Bh, Bl, bm, bn);
    CP_COMMIT();

    #pragma unroll 1
    for (int it = 0; it < GNIT; it++) {
        const uint32_t bufo = (uint32_t)(it % 3) * STG_B;
        if (it + 2 < GNIT) {
            gemm_stage(sbase, (uint32_t)((it + 2) % 3) * STG_B, tid,
                       (it + 2) * GBK, Ah, Bh, Bl, bm, bn);
            CP_COMMIT();
            CP_WAIT(2);
        } else if (it + 1 < GNIT) {
            CP_WAIT(1);
        } else {
            CP_WAIT(0);
        }
        __syncthreads();

        // rolling-prefetch micro-steps: 8 steps (ks x nt), 8 MMAs each.
        uint32_t fa[2][8], fb[2][8];
        gemm_load_a(fa[0], 0, a_l + bufo);
        gemm_load_b(fb[0], 0, 0, b_l + bufo);

        #pragma unroll
        for (int s = 0; s < 8; s++) {
            const int nt = s & 3;
            const int ab = s >> 2;
            const int bb = s & 1;
            if (s < 7)
                gemm_load_b(fb[bb ^ 1], (s + 1) >> 2, (s + 1) & 3, b_l + bufo);
            if (s == 3)
                gemm_load_a(fa[1], 1, a_l + bufo);

            MMA16816(acc[0][2*nt],   &fa[ab][0], fb[bb][0], fb[bb][1]);
            MMA16816(acc[0][2*nt+1], &fa[ab][0], fb[bb][2], fb[bb][3]);
            MMA16816(acc[1][2*nt],   &fa[ab][4], fb[bb][0], fb[bb][1]);
            MMA16816(acc[1][2*nt+1], &fa[ab][4], fb[bb][2], fb[bb][3]);
            MMA16816(acc[0][2*nt],   &fa[ab][0], fb[bb][4], fb[bb][5]);
            MMA16816(acc[0][2*nt+1], &fa[ab][0], fb[bb][6], fb[bb][7]);
            MMA16816(acc[1][2*nt],   &fa[ab][4], fb[bb][4], fb[bb][5]);
            MMA16816(acc[1][2*nt+1], &fa[ab][4], fb[bb][6], fb[bb][7]);
        }
        __syncthreads();
    }
}

// ---- fused QKV projection ----
__global__ __launch_bounds__(256, 2)
void qkv_mma(const __half* __restrict__ xh,
             const __half* __restrict__ wh, const __half* __restrict__ wl,
             __half* __restrict__ qh,
             __half* __restrict__ kh, __half* __restrict__ kl,
             __half* __restrict__ vh, __half* __restrict__ vl)
{
    extern __shared__ char sm[];
    const uint32_t sbase = smem_u32(sm);
    const int tid = threadIdx.x;
    const int z   = blockIdx.z;
    const int bm  = blockIdx.y * 128;
    const int bn  = blockIdx.x * 128;
    const size_t WN = (size_t)D_MODEL * D_MODEL;

    float acc[2][8][4];
    #pragma unroll
    for (int i = 0; i < 2; i++)
        #pragma unroll
        for (int j = 0; j < 8; j++)
            #pragma unroll
            for (int r = 0; r < 4; r++) acc[i][j][r] = 0.f;

    gemm_mainloop(xh, wh + (size_t)z * WN, wl + (size_t)z * WN,
                  bm, bn, sbase, tid, acc);

    const int lane = tid & 31;
    const int wid  = tid >> 5;
    const int g    = lane >> 2;
    const int q4   = (lane & 3) * 2;

    if (z == 0) {
        // Q: single fp16, pre-scaled by 1/8
        #pragma unroll
        for (int im = 0; im < 2; im++) {
            const int r0 = bm + (wid & 3) * 32 + im * 16 + g;
            #pragma unroll
            for (int in = 0; in < 8; in++) {
                const int c = bn + (wid >> 2) * 64 + in * 8 + q4;
                *(uint32_t*)(qh + (size_t)r0 * D_MODEL + c) =
                    cvt2h(acc[im][in][0] * 0.125f, acc[im][in][1] * 0.125f);
                *(uint32_t*)(qh + (size_t)(r0 + 8) * D_MODEL + c) =
                    cvt2h(acc[im][in][2] * 0.125f, acc[im][in][3] * 0.125f);
            }
        }
    } else {
        __half* Ch = (z == 1) ? kh : vh;
        __half* Cl = (z == 1) ? kl : vl;
        #pragma unroll
        for (int im = 0; im < 2; im++) {
            const int r0 = bm + (wid & 3) * 32 + im * 16 + g;
            #pragma unroll
            for (int in = 0; in < 8; in++) {
                const int c = bn + (wid >> 2) * 64 + in * 8 + q4;
                uint32_t h, l;
                split2h(acc[im][in][0], acc[im][in][1], h, l);
                *(uint32_t*)(Ch + (size_t)r0 * D_MODEL + c) = h;
                *(uint32_t*)(Cl + (size_t)r0 * D_MODEL + c) = l;
                split2h(acc[im][in][2], acc[im][in][3], h, l);
                *(uint32_t*)(Ch + (size_t)(r0 + 8) * D_MODEL + c) = h;
                *(uint32_t*)(Cl + (size_t)(r0 + 8) * D_MODEL + c) = l;
            }
        }
    }
}

// ---- output projection: fp32 out + bias ----
__global__ __launch_bounds__(256, 2)
void oproj_mma(const __half* __restrict__ Ah,
               const __half* __restrict__ Bh, const __half* __restrict__ Bl,
               const float* __restrict__ bias,
               float* __restrict__ C)
{
    extern __shared__ char sm[];
    const uint32_t sbase = smem_u32(sm);
    const int tid = threadIdx.x;
    const int bm  = blockIdx.y * 128;
    const int bn  = blockIdx.x * 128;

    float acc[2][8][4];
    #pragma unroll
    for (int i = 0; i < 2; i++)
        #pragma unroll
        for (int j = 0; j < 8; j++)
            #pragma unroll
            for (int r = 0; r < 4; r++) acc[i][j][r] = 0.f;

    gemm_mainloop(Ah, Bh, Bl, bm, bn, sbase, tid, acc);

    const int lane = tid & 31;
    const int wid  = tid >> 5;
    const int g    = lane >> 2;
    const int q4   = (lane & 3) * 2;
    #pragma unroll
    for (int im = 0; im < 2; im++) {
        const int r0 = bm + (wid & 3) * 32 + im * 16 + g;
        #pragma unroll
        for (int in = 0; in < 8; in++) {
            const int c = bn + (wid >> 2) * 64 + in * 8 + q4;
            const float b0 = bias[c], b1 = bias[c + 1];
            *(float2*)(C + (size_t)r0 * D_MODEL + c) =
                make_float2(acc[im][in][0] + b0, acc[im][in][1] + b1);
            *(float2*)(C + (size_t)(r0 + 8) * D_MODEL + c) =
                make_float2(acc[im][in][2] + b0, acc[im][in][3] + b1);
        }
    }
}

// ======================================================================
// Tensor-core causal flash attention. Q/P single fp16; K/V fp16 pairs.
// ======================================================================
#define APITCH 144
#define KV0   (128 * APITCH)            // 18432 (Q single mat)
#define KVMAT (64 * APITCH)             // 9216
#define KVBUF (4 * KVMAT)               // 36864 (KH, KL, VH, VL)
#define ASMEM (KV0 + 2 * KVBUF)         // 92160

__device__ __forceinline__ void attn_stage_kv(
    uint32_t dst, int tid, const __half* Kh, const __half* Kl,
    const __half* Vh, const __half* Vl,
    size_t gbase, int k0)
{
    #pragma unroll
    for (int i = 0; i < 2; i++) {
        const int id  = tid + 256 * i;        // 0..511
        const int row = id >> 3;              // 0..63
        const int c16 = id & 7;
        const uint32_t so = dst + (uint32_t)(row * APITCH + c16 * 16);
        const size_t gk = gbase + (size_t)(k0 + row) * D_MODEL + c16 * 8;
        CP_ASYNC16(so,             Kh + gk);
        CP_ASYNC16(so + KVMAT,     Kl + gk);
        CP_ASYNC16(so + 2 * KVMAT, Vh + gk);
        CP_ASYNC16(so + 3 * KVMAT, Vl + gk);
    }
}

__global__ __launch_bounds__(256, 2)
void attn_mma(const __half* __restrict__ Qh,
              const __half* __restrict__ Kh, const __half* __restrict__ Kl,
              const __half* __restrict__ Vh, const __half* __restrict__ Vl,
              __half* __restrict__ Oh)
{
    extern __shared__ char sm[];
    const uint32_t sbase = smem_u32(sm);

    const int tid  = threadIdx.x;
    const int lane = tid & 31;
    const int wid  = tid >> 5;
    const int g    = lane >> 2;
    const int tg   = lane & 3;
    const int qb   = gridDim.x - 1 - blockIdx.x;   // heavy blocks first
    const int bh   = blockIdx.y;
    const size_t base = (size_t)(bh >> 4) * SEQ * D_MODEL + (size_t)(bh & 15) * DK;

    const int qbase = qb * 128 + wid * 16;

    // ---- stage Q (single fp16, once) ----
    #pragma unroll
    for (int i = 0; i < 4; i++) {
        const int id  = tid + 256 * i;        // 0..1023
        const int row = id >> 3;
        const int c16 = id & 7;
        const uint32_t so = sbase + (uint32_t)(row * APITCH + c16 * 16);
        const size_t gq = base + (size_t)(qb * 128 + row) * D_MODEL + c16 * 8;
        CP_ASYNC16(so, Qh + gq);
    }
    attn_stage_kv(sbase + KV0, tid, Kh, Kl, Vh, Vl, base, 0);
    CP_COMMIT();

    float oacc[8][4];
    #pragma unroll
    for (int i = 0; i < 8; i++)
        #pragma unroll
        for (int r = 0; r < 4; r++) oacc[i][r] = 0.f;
    float m0 = -1e30f, m1 = -1e30f, l0 = 0.f, l1 = 0.f;

    const uint32_t qa = sbase + (uint32_t)((wid * 16 + (lane & 15)) * APITCH
                                           + (lane >> 4) * 16);
    const uint32_t ka_l = (uint32_t)(((lane & 7) + ((lane >> 4) << 3)) * APITCH
                                           + ((lane >> 3) & 1) * 16);
    const uint32_t va_l = (uint32_t)((lane & 15) * APITCH + (lane >> 4) * 16);

    const int ntiles = 2 * qb + 2;

    #pragma unroll 1
    for (int t = 0; t < ntiles; t++) {
        const int k0 = t * 64;
        const uint32_t kvb = sbase + KV0 + (uint32_t)(t & 1) * KVBUF;

        if (t + 1 < ntiles) {
            attn_stage_kv(sbase + KV0 + (uint32_t)((t + 1) & 1) * KVBUF,
                          tid, Kh, Kl, Vh, Vl, base, (t + 1) * 64);
            CP_COMMIT();
            CP_WAIT(1);
        } else {
            CP_WAIT(0);
        }
        __syncthreads();

        const bool active = (k0 <= qbase + 15);
        if (active) {
            // ---- S = Q @ K^T (2-term: Qh·Kh + Qh·Kl) ----
            float sacc[8][4];
            #pragma unroll
            for (int i = 0; i < 8; i++)
                #pragma unroll
                for (int r = 0; r < 4; r++) sacc[i][r] = 0.f;

            const uint32_t ka = kvb + ka_l;
            #pragma unroll
            for (int kk = 0; kk < 4; kk++) {
                const uint32_t ko = (uint32_t)(kk * 32);
                uint32_t ah[4];
                LDSM_X4(ah[0], ah[1], ah[2], ah[3], qa + ko);
                #pragma unroll
                for (int nt = 0; nt < 4; nt++) {
                    uint32_t ba = ka + ko + (uint32_t)(nt * 16 * APITCH);
                    uint32_t kh[4], kl[4];
                    LDSM_X4(kh[0], kh[1], kh[2], kh[3], ba);
                    LDSM_X4(kl[0], kl[1], kl[2], kl[3], ba + KVMAT);
                    MMA16816(sacc[2*nt],   ah, kh[0], kh[1]);
                    MMA16816(sacc[2*nt+1], ah, kh[2], kh[3]);
                    MMA16816(sacc[2*nt],   ah, kl[0], kl[1]);
                    MMA16816(sacc[2*nt+1], ah, kl[2], kl[3]);
                }
            }

            // ---- causal mask ----
            if (t + 2 >= ntiles) {
                const int qi0 = qbase + g;
                const int qi1 = qbase + g + 8;
                #pragma unroll
                for (int dn = 0; dn < 8; dn++) {
                    const int kc = k0 + dn * 8 + tg * 2;
                    if (kc     > qi0) sacc[dn][0] = -1e30f;
                    if (kc + 1 > qi0) sacc[dn][1] = -1e30f;
                    if (kc     > qi1) sacc[dn][2] = -1e30f;
                    if (kc + 1 > qi1) sacc[dn][3] = -1e30f;
                }
            }

            // ---- online softmax ----
            float r0 = -1e30f, r1 = -1e30f;
            #pragma unroll
            for (int dn = 0; dn < 8; dn++) {
                r0 = fmaxf(r0, fmaxf(sacc[dn][0], sacc[dn][1]));
                r1 = fmaxf(r1, fmaxf(sacc[dn][2], sacc[dn][3]));
            }
            r0 = fmaxf(r0, __shfl_xor_sync(0xFFFFFFFFu, r0, 1));
            r0 = fmaxf(r0, __shfl_xor_sync(0xFFFFFFFFu, r0, 2));
            r1 = fmaxf(r1, __shfl_xor_sync(0xFFFFFFFFu, r1, 1));
            r1 = fmaxf(r1, __shfl_xor_sync(0xFFFFFFFFu, r1, 2));
            const float nm0 = fmaxf(m0, r0), nm1 = fmaxf(m1, r1);
            const float c0 = __expf(m0 - nm0), c1 = __expf(m1 - nm1);
            m0 = nm0; m1 = nm1;
            l0 *= c0;  l1 *= c1;
            #pragma unroll
            for (int dn = 0; dn < 8; dn++) {
                oacc[dn][0] *= c0; oacc[dn][1] *= c0;
                oacc[dn][2] *= c1; oacc[dn][3] *= c1;
            }
            #pragma unroll
            for (int dn = 0; dn < 8; dn++) {
                float p0 = __expf(sacc[dn][0] - m0);
                float p1 = __expf(sacc[dn][1] - m0);
                float p2 = __expf(sacc[dn][2] - m1);
                float p3 = __expf(sacc[dn][3] - m1);
                sacc[dn][0] = p0; sacc[dn][1] = p1;
                sacc[dn][2] = p2; sacc[dn][3] = p3;
                l0 += p0 + p1; l1 += p2 + p3;
            }

            // ---- O += P @ V (2-term: Ph·Vh + Ph·Vl, P single fp16) ----
            const uint32_t va = kvb + 2 * KVMAT + va_l;
            #pragma unroll
            for (int kk = 0; kk < 4; kk++) {
                uint32_t ph[4];
                ph[0] = cvt2h(sacc[2*kk][0],   sacc[2*kk][1]);
                ph[1] = cvt2h(sacc[2*kk][2],   sacc[2*kk][3]);
                ph[2] = cvt2h(sacc[2*kk+1][0], sacc[2*kk+1][1]);
                ph[3] = cvt2h(sacc[2*kk+1][2], sacc[2*kk+1][3]);
                #pragma unroll
                for (int dn = 0; dn < 4; dn++) {
                    uint32_t a = va + (uint32_t)(kk * 16 * APITCH + dn * 32);
                    uint32_t vh[4], vl[4];
                    LDSM_X4_T(vh[0], vh[1], vh[2], vh[3], a);
                    LDSM_X4_T(vl[0], vl[1], vl[2], vl[3], a + KVMAT);
                    MMA16816(oacc[2*dn],   ph, vh[0], vh[1]);
                    MMA16816(oacc[2*dn+1], ph, vh[2], vh[3]);
                    MMA16816(oacc[2*dn],   ph, vl[0], vl[1]);
                    MMA16816(oacc[2*dn+1], ph, vl[2], vl[3]);
                }
            }
        }
        __syncthreads();
    }

    // ---- epilogue: normalize, store single fp16 ----
    l0 += __shfl_xor_sync(0xFFFFFFFFu, l0, 1);
    l0 += __shfl_xor_sync(0xFFFFFFFFu, l0, 2);
    l1 += __shfl_xor_sync(0xFFFFFFFFu, l1, 1);
    l1 += __shfl_xor_sync(0xFFFFFFFFu, l1, 2);
    const float inv0 = 1.f / l0, inv1 = 1.f / l1;

    const size_t o0 = base + (size_t)(qbase + g) * D_MODEL + tg * 2;
    const size_t o1 = o0 + 8 * D_MODEL;
    #pragma unroll
    for (int dn = 0; dn < 8; dn++) {
        *(uint32_t*)(Oh + o0 + dn * 8) = cvt2h(oacc[dn][0] * inv0, oacc[dn][1] * inv0);
        *(uint32_t*)(Oh + o1 + dn * 8) = cvt2h(oacc[dn][2] * inv1, oacc[dn][3] * inv1);
    }
}

// ======================================================================
extern "C" void kernel_launch(void* const* d_in, const int* in_sizes, int n_in,
                              void* d_out, int out_size)
{
    const float* x   = (const float*)d_in[0];
    const float* w_q = (const float*)d_in[1];
    const float* w_k = (const float*)d_in[2];
    const float* w_v = (const float*)d_in[3];
    const float* w_o = (const float*)d_in[4];
    const float* b_o = (const float*)d_in[5];
    float* out = (float*)d_out;

    __half *xh, *qh, *kh, *kl, *vh, *vl, *aoh, *wh, *wl;
    cudaGetSymbolAddress((void**)&xh,  g_xh);
    cudaGetSymbolAddress((void**)&qh,  g_qh);
    cudaGetSymbolAddress((void**)&kh,  g_kh);
    cudaGetSymbolAddress((void**)&kl,  g_kl);
    cudaGetSymbolAddress((void**)&vh,  g_vh);
    cudaGetSymbolAddress((void**)&vl,  g_vl);
    cudaGetSymbolAddress((void**)&aoh, g_aoh);
    cudaGetSymbolAddress((void**)&wh,  g_wh);
    cudaGetSymbolAddress((void**)&wl,  g_wl);

    cudaFuncSetAttribute(qkv_mma,   cudaFuncAttributeMaxDynamicSharedMemorySize, GSMEM);
    cudaFuncSetAttribute(oproj_mma, cudaFuncAttributeMaxDynamicSharedMemorySize, GSMEM);
    cudaFuncSetAttribute(attn_mma,  cudaFuncAttributeMaxDynamicSharedMemorySize, ASMEM);

    const size_t WN = (size_t)D_MODEL * D_MODEL;

    presplit_all<<<MROWS + 4 * (int)(WN / 1024), 256>>>(
        x, w_q, w_k, w_v, w_o, xh, wh, wl);

    dim3 qgrid(D_MODEL / 128, MROWS / 128, 3);   // (8, 64, 3)
    qkv_mma<<<qgrid, 256, GSMEM>>>(xh, wh, wl, qh, kh, kl, vh, vl);

    dim3 agrid(SEQ / 128, BATCH * NHEADS);       // (16, 64)
    attn_mma<<<agrid, 256, ASMEM>>>(qh, kh, kl, vh, vl, aoh);

    dim3 ogrid(D_MODEL / 128, MROWS / 128);      // (8, 64)
    oproj_mma<<<ogrid, 256, GSMEM>>>(aoh, wh + 3 * WN, wl + 3 * WN, b_o, out);
}